// round 1
// baseline (speedup 1.0000x reference)
#include <cuda_runtime.h>
#include <math.h>

#define BB 8
#define NN 4096
#define KKN 20
#define BN_TOTAL (BB*NN)          // 32768
#define R_EDGE (BB*NN*KKN)        // 655360
#define EPSI 1e-5f

// ---------------- scratch (device globals; no allocation allowed) ------------
__device__ float  g_h[R_EDGE*128];          // 335 MB activation scratch
__device__ float  g_x1[BN_TOTAL*64];        // edgeconv1 output
__device__ float  g_x2[BN_TOTAL*128];       // edgeconv2 output
__device__ int    g_idx[R_EDGE];            // knn indices (reused per stage)
__device__ double g_sum[5][128];
__device__ double g_ssq[5][128];
__device__ float  g_scale[5][128];
__device__ float  g_shift[5][128];

// ---------------- zero stats -------------------------------------------------
__global__ void zero_stats_kernel() {
    int t = blockIdx.x * blockDim.x + threadIdx.x;
    if (t < 5*128) { (&g_sum[0][0])[t] = 0.0; (&g_ssq[0][0])[t] = 0.0; }
}

// ---------------- fused distance + top-k (k=20) ------------------------------
// One thread per query point i. Tile of 128 j-points staged in smem as float4.
// Strict '<' insertion scanning j ascending replicates jax top_k tie-breaking
// (lower index wins on equal distance).
template<int C>
__global__ void knn_kernel(const float* __restrict__ Xin, int* __restrict__ out_idx) {
    constexpr int C4 = C / 4;
    constexpr int TI = 128, TJ = 128;
    __shared__ float4 sxj[TJ * C4];
    __shared__ float  sx2[TJ];

    const float* Xs = (C == 4) ? Xin : (const float*)g_x1;
    const float4* X4 = (const float4*)Xs;

    int b = blockIdx.x / (NN / TI);
    int i = (blockIdx.x % (NN / TI)) * TI + threadIdx.x;

    float4 xi[C4];
#pragma unroll
    for (int q = 0; q < C4; q++) xi[q] = X4[(size_t)(b*NN + i)*C4 + q];
    float x2i = 0.f;
#pragma unroll
    for (int q = 0; q < C4; q++)
        x2i += xi[q].x*xi[q].x + xi[q].y*xi[q].y + xi[q].z*xi[q].z + xi[q].w*xi[q].w;

    float td[KKN]; int ti[KKN];
#pragma unroll
    for (int s = 0; s < KKN; s++) { td[s] = 3.4e38f; ti[s] = 0; }

    for (int j0 = 0; j0 < NN; j0 += TJ) {
        __syncthreads();
        for (int e = threadIdx.x; e < TJ*C4; e += TI)
            sxj[e] = X4[(size_t)(b*NN + j0)*C4 + e];
        __syncthreads();
        {   // per-row |x|^2
            int row = threadIdx.x;
            float s2 = 0.f;
#pragma unroll
            for (int q = 0; q < C4; q++) {
                float4 v = sxj[row*C4 + q];
                s2 += v.x*v.x + v.y*v.y + v.z*v.z + v.w*v.w;
            }
            sx2[row] = s2;
        }
        __syncthreads();
        for (int jj = 0; jj < TJ; jj++) {
            float dot = 0.f;
#pragma unroll
            for (int q = 0; q < C4; q++) {
                float4 v = sxj[jj*C4 + q];
                dot += xi[q].x*v.x + xi[q].y*v.y + xi[q].z*v.z + xi[q].w*v.w;
            }
            float d = x2i + sx2[jj] - 2.0f*dot;
            if (d < td[KKN-1]) {
                td[KKN-1] = d; ti[KKN-1] = j0 + jj;
#pragma unroll
                for (int s = KKN-1; s > 0; s--) {
                    if (td[s] < td[s-1]) {
                        float t0 = td[s]; td[s] = td[s-1]; td[s-1] = t0;
                        int   u0 = ti[s]; ti[s] = ti[s-1]; ti[s-1] = u0;
                    }
                }
            }
        }
    }
#pragma unroll
    for (int s = 0; s < KKN; s++) out_idx[(size_t)(b*NN + i)*KKN + s] = ti[s];
}

// ---------------- edgeconv1 layer1: msg(8) @ W(8x64) + stats -----------------
__global__ void c1_phase1_kernel(const float* __restrict__ X,
                                 const float* __restrict__ W,
                                 const float* __restrict__ bias) {
    __shared__ float sW[8*64];
    __shared__ float sB[64];
    __shared__ float sS[64], sQ[64];
    int tid = threadIdx.x;
    if (tid < 64) { sB[tid] = bias[tid]; sS[tid] = 0.f; sQ[tid] = 0.f; }
    for (int e = tid; e < 512; e += 256) sW[e] = W[e];
    __syncthreads();

    int r  = blockIdx.x * 256 + tid;        // r < R_EDGE (2560 blocks)
    int bn = r / KKN;
    int b  = bn / NN;
    int j  = g_idx[r];
    float msg[8];
#pragma unroll
    for (int c = 0; c < 4; c++) {
        float xi = X[bn*4 + c];
        float xj = X[(size_t)(b*NN + j)*4 + c];
        msg[c] = xi; msg[4+c] = xj - xi;
    }
    int lane = tid & 31;
    float* orow = &g_h[(size_t)r * 64];
#pragma unroll
    for (int co4 = 0; co4 < 16; co4++) {
        float a[4];
#pragma unroll
        for (int u = 0; u < 4; u++) {
            int co = co4*4 + u;
            float acc = sB[co];
#pragma unroll
            for (int ci = 0; ci < 8; ci++) acc = fmaf(msg[ci], sW[ci*64 + co], acc);
            a[u] = acc;
        }
        *(float4*)&orow[co4*4] = make_float4(a[0], a[1], a[2], a[3]);
#pragma unroll
        for (int u = 0; u < 4; u++) {
            float s = a[u], q = a[u]*a[u];
#pragma unroll
            for (int o = 16; o > 0; o >>= 1) {
                s += __shfl_down_sync(0xffffffffu, s, o);
                q += __shfl_down_sync(0xffffffffu, q, o);
            }
            if (lane == 0) { atomicAdd(&sS[co4*4+u], s); atomicAdd(&sQ[co4*4+u], q); }
        }
    }
    __syncthreads();
    if (tid < 64) {
        atomicAdd(&g_sum[0][tid], (double)sS[tid]);
        atomicAdd(&g_ssq[0][tid], (double)sQ[tid]);
    }
}

// ---------------- finalize BN fold: scale/shift ------------------------------
__global__ void finalize_kernel(int stage, const float* __restrict__ gam,
                                const float* __restrict__ bet, float n, int cout) {
    int c = threadIdx.x;
    if (c < cout) {
        double mean = g_sum[stage][c] / (double)n;
        double var  = g_ssq[stage][c] / (double)n - mean*mean;
        float  s    = gam[c] / sqrtf((float)var + EPSI);
        g_scale[stage][c] = s;
        g_shift[stage][c] = bet[c] - (float)mean * s;
    }
}

// ---------------- tiled GEMM with fused A-gather/BN-relu + stats -------------
// MODE 0: A = [x_i, x_j - x_i] gathered from g_x1 via g_idx   (edgeconv2 L1)
// MODE 1: A = relu(g_h * scale + shift)  (in-place layer2; block owns rows)
// MODE 2: A = concat(g_x1, g_x2)                               (classifier L1)
// out is always g_h. Epilogue streams per-channel sum/sum^2 for the next BN.
template<int CIN, int COUT, int MODE>
__global__ void __launch_bounds__(256)
gemm_stats_kernel(int sstage, int pstage,
                  const float* __restrict__ W, const float* __restrict__ bias) {
    constexpr int BM = 128, BK = 32;
    constexpr int TN = COUT / 16;
    __shared__ float As[BK][BM + 1];
    __shared__ float Bs[BK][COUT];
    __shared__ float sS[COUT], sQ[COUT];

    int tid = threadIdx.x;
    int tx = tid & 15, ty = tid >> 4;
    if (tid < COUT) { sS[tid] = 0.f; sQ[tid] = 0.f; }
    int r0 = blockIdx.x * BM;

    float acc[8][TN];
#pragma unroll
    for (int i = 0; i < 8; i++)
#pragma unroll
        for (int j = 0; j < TN; j++) acc[i][j] = 0.f;

    for (int kt = 0; kt < CIN/BK; kt++) {
#pragma unroll
        for (int e0 = 0; e0 < BM*BK; e0 += 256) {
            int e = e0 + tid;
            int m = e >> 5, k = e & 31;
            int kc = kt*BK + k;
            int r = r0 + m;
            float v;
            if constexpr (MODE == 0) {
                constexpr int C = CIN/2;
                int bn = r / KKN;
                int b  = bn / NN;
                int j  = g_idx[r];
                if (kc < C) v = g_x1[(size_t)bn*C + kc];
                else        v = g_x1[(size_t)(b*NN + j)*C + (kc - C)]
                              - g_x1[(size_t)bn*C + (kc - C)];
            } else if constexpr (MODE == 1) {
                float h = g_h[(size_t)r*CIN + kc];
                v = fmaxf(fmaf(h, g_scale[pstage][kc], g_shift[pstage][kc]), 0.f);
            } else {
                v = (kc < 64) ? g_x1[(size_t)r*64 + kc]
                              : g_x2[(size_t)r*128 + (kc - 64)];
            }
            As[k][m] = v;
        }
#pragma unroll
        for (int e0 = 0; e0 < BK*COUT; e0 += 256) {
            int e = e0 + tid;
            int k = e / COUT, n = e % COUT;
            Bs[k][n] = W[(size_t)(kt*BK + k)*COUT + n];
        }
        __syncthreads();
#pragma unroll
        for (int k = 0; k < BK; k++) {
            float a[8], bb[TN];
#pragma unroll
            for (int i = 0; i < 8; i++) a[i] = As[k][ty*8 + i];
#pragma unroll
            for (int j = 0; j < TN; j++) bb[j] = Bs[k][j*16 + tx];
#pragma unroll
            for (int i = 0; i < 8; i++)
#pragma unroll
                for (int j = 0; j < TN; j++) acc[i][j] = fmaf(a[i], bb[j], acc[i][j]);
        }
        __syncthreads();
    }
#pragma unroll
    for (int j = 0; j < TN; j++) {
        int col = j*16 + tx;
        float bv = bias[col];
        float s = 0.f, q = 0.f;
#pragma unroll
        for (int i = 0; i < 8; i++) {
            int row = r0 + ty*8 + i;
            float v = acc[i][j] + bv;
            g_h[(size_t)row*COUT + col] = v;
            s += v; q += v*v;
        }
        atomicAdd(&sS[col], s); atomicAdd(&sQ[col], q);
    }
    __syncthreads();
    if (tid < COUT) {
        atomicAdd(&g_sum[sstage][tid], (double)sS[tid]);
        atomicAdd(&g_ssq[sstage][tid], (double)sQ[tid]);
    }
}

// ---------------- BN+relu + max over k --------------------------------------
template<int COUT>
__global__ void maxpool_kernel(int pstage) {
    int t = blockIdx.x * 256 + threadIdx.x;      // t < BN_TOTAL*COUT
    int c  = t & (COUT - 1);
    int bn = t >> (COUT == 64 ? 6 : 7);
    float s  = g_scale[pstage][c], sh = g_shift[pstage][c];
    const float* base = &g_h[((size_t)bn * KKN) * COUT + c];
    float m = -3.4e38f;
#pragma unroll
    for (int kk = 0; kk < KKN; kk++)
        m = fmaxf(m, fmaf(base[(size_t)kk*COUT], s, sh));
    m = fmaxf(m, 0.f);
    if (COUT == 64) g_x1[t] = m; else g_x2[t] = m;
}

// ---------------- classifier final: relu(bn(h)) @ w2 + b2 -------------------
__global__ void cls_final_kernel(const float* __restrict__ W2,
                                 const float* __restrict__ B2,
                                 float* __restrict__ out) {
    int gw   = (blockIdx.x * blockDim.x + threadIdx.x) >> 5;  // row, < 32768
    int lane = threadIdx.x & 31;
    const float* hrow = &g_h[(size_t)gw * 128];
    float p = 0.f;
#pragma unroll
    for (int q = 0; q < 4; q++) {
        int c = lane + 32*q;
        float v = fmaxf(fmaf(hrow[c], g_scale[4][c], g_shift[4][c]), 0.f);
        p = fmaf(v, W2[c], p);
    }
#pragma unroll
    for (int o = 16; o > 0; o >>= 1) p += __shfl_down_sync(0xffffffffu, p, o);
    if (lane == 0) out[gw] = p + B2[0];
}

// ---------------- host orchestration ----------------------------------------
extern "C" void kernel_launch(void* const* d_in, const int* in_sizes, int n_in,
                              void* d_out, int out_size) {
    const float* x      = (const float*)d_in[0];
    const float* c1_w1  = (const float*)d_in[1];
    const float* c1_b1  = (const float*)d_in[2];
    const float* c1_g1  = (const float*)d_in[3];
    const float* c1_be1 = (const float*)d_in[4];
    const float* c1_w2  = (const float*)d_in[5];
    const float* c1_b2  = (const float*)d_in[6];
    const float* c1_g2  = (const float*)d_in[7];
    const float* c1_be2 = (const float*)d_in[8];
    const float* c2_w1  = (const float*)d_in[9];
    const float* c2_b1  = (const float*)d_in[10];
    const float* c2_g1  = (const float*)d_in[11];
    const float* c2_be1 = (const float*)d_in[12];
    const float* c2_w2  = (const float*)d_in[13];
    const float* c2_b2  = (const float*)d_in[14];
    const float* c2_g2  = (const float*)d_in[15];
    const float* c2_be2 = (const float*)d_in[16];
    const float* cls_w1 = (const float*)d_in[17];
    const float* cls_b1 = (const float*)d_in[18];
    const float* cls_g1 = (const float*)d_in[19];
    const float* cls_be1= (const float*)d_in[20];
    const float* cls_w2 = (const float*)d_in[21];
    const float* cls_b2 = (const float*)d_in[22];
    float* out = (float*)d_out;

    int* idx_ptr;
    cudaGetSymbolAddress((void**)&idx_ptr, g_idx);

    zero_stats_kernel<<<3, 256>>>();

    // ---- EdgeConv 1 ----
    knn_kernel<4><<<BB*(NN/128), 128>>>(x, idx_ptr);
    c1_phase1_kernel<<<R_EDGE/256, 256>>>(x, c1_w1, c1_b1);
    finalize_kernel<<<1, 128>>>(0, c1_g1, c1_be1, (float)R_EDGE, 64);
    gemm_stats_kernel<64, 64, 1><<<R_EDGE/128, 256>>>(1, 0, c1_w2, c1_b2);
    finalize_kernel<<<1, 128>>>(1, c1_g2, c1_be2, (float)R_EDGE, 64);
    maxpool_kernel<64><<<BN_TOTAL*64/256, 256>>>(1);

    // ---- EdgeConv 2 ----
    knn_kernel<64><<<BB*(NN/128), 128>>>(x, idx_ptr);
    gemm_stats_kernel<128, 128, 0><<<R_EDGE/128, 256>>>(2, 0, c2_w1, c2_b1);
    finalize_kernel<<<1, 128>>>(2, c2_g1, c2_be1, (float)R_EDGE, 128);
    gemm_stats_kernel<128, 128, 1><<<R_EDGE/128, 256>>>(3, 2, c2_w2, c2_b2);
    finalize_kernel<<<1, 128>>>(3, c2_g2, c2_be2, (float)R_EDGE, 128);
    maxpool_kernel<128><<<BN_TOTAL*128/256, 256>>>(3);

    // ---- Classifier ----
    gemm_stats_kernel<192, 128, 2><<<BN_TOTAL/128, 256>>>(4, 0, cls_w1, cls_b1);
    finalize_kernel<<<1, 128>>>(4, cls_g1, cls_be1, (float)BN_TOTAL, 128);
    cls_final_kernel<<<BN_TOTAL/8, 256>>>(cls_w2, cls_b2, out);
}

// round 3
// speedup vs baseline: 1.0179x; 1.0179x over previous
#include <cuda_runtime.h>
#include <math.h>
#include <stdint.h>

#define BB 8
#define NN 4096
#define KKN 20
#define BN_TOTAL (BB*NN)          // 32768
#define R_EDGE (BB*NN*KKN)        // 655360
#define EPSI 1e-5f

// ---------------- scratch (device globals; no allocation allowed) ------------
__device__ float  g_h[(size_t)R_EDGE*128];  // activation scratch
__device__ float  g_x1[BN_TOTAL*64];        // edgeconv1 output
__device__ float  g_x2[BN_TOTAL*128];       // edgeconv2 output
__device__ int    g_idx[R_EDGE];            // knn indices (reused per stage)
__device__ double g_sum[5][128];
__device__ double g_ssq[5][128];
__device__ float  g_scale[5][128];
__device__ float  g_shift[5][128];

// ---------------- helpers -----------------------------------------------------
__device__ __forceinline__ void tf32_split(float v, float& hi, float& lo) {
    uint32_t h; asm("cvt.rna.tf32.f32 %0, %1;" : "=r"(h) : "f"(v));
    hi = __uint_as_float(h);
    uint32_t l; asm("cvt.rna.tf32.f32 %0, %1;" : "=r"(l) : "f"(v - hi));
    lo = __uint_as_float(l);
}
// D += A(16x8, row) * B(8x8, col);  tf32 operands as b32 regs
__device__ __forceinline__ void mma8(float* c, const uint32_t* a, const uint32_t* b) {
    asm volatile("mma.sync.aligned.m16n8k8.row.col.f32.tf32.tf32.f32 "
        "{%0,%1,%2,%3}, {%4,%5,%6,%7}, {%8,%9}, {%0,%1,%2,%3};"
        : "+f"(c[0]), "+f"(c[1]), "+f"(c[2]), "+f"(c[3])
        : "r"(a[0]), "r"(a[1]), "r"(a[2]), "r"(a[3]), "r"(b[0]), "r"(b[1]));
}

// ---------------- zero stats -------------------------------------------------
__global__ void zero_stats_kernel() {
    int t = blockIdx.x * blockDim.x + threadIdx.x;
    if (t < 5*128) { (&g_sum[0][0])[t] = 0.0; (&g_ssq[0][0])[t] = 0.0; }
}

// ---------------- knn for C=4 (first edgeconv): SIMT, cheap ------------------
__global__ void knn4_kernel(const float* __restrict__ Xin, int* __restrict__ out_idx) {
    constexpr int TI = 128, TJ = 128;
    __shared__ float4 sxj[TJ];
    __shared__ float  sx2[TJ];
    const float4* X4 = (const float4*)Xin;

    int b = blockIdx.x / (NN / TI);
    int i = (blockIdx.x % (NN / TI)) * TI + threadIdx.x;

    float4 xi = X4[(size_t)b*NN + i];
    float x2i = xi.x*xi.x + xi.y*xi.y + xi.z*xi.z + xi.w*xi.w;

    float td[KKN]; int ti[KKN];
#pragma unroll
    for (int s = 0; s < KKN; s++) { td[s] = 3.4e38f; ti[s] = 0; }

    for (int j0 = 0; j0 < NN; j0 += TJ) {
        __syncthreads();
        {
            float4 v = X4[(size_t)b*NN + j0 + threadIdx.x];
            sxj[threadIdx.x] = v;
            sx2[threadIdx.x] = v.x*v.x + v.y*v.y + v.z*v.z + v.w*v.w;
        }
        __syncthreads();
        for (int jj = 0; jj < TJ; jj++) {
            float4 v = sxj[jj];
            float dot = xi.x*v.x + xi.y*v.y + xi.z*v.z + xi.w*v.w;
            float d = x2i + sx2[jj] - 2.0f*dot;
            if (d < td[KKN-1]) {
                td[KKN-1] = d; ti[KKN-1] = j0 + jj;
#pragma unroll
                for (int s = KKN-1; s > 0; s--) {
                    if (td[s] < td[s-1]) {
                        float t0 = td[s]; td[s] = td[s-1]; td[s-1] = t0;
                        int   u0 = ti[s]; ti[s] = ti[s-1]; ti[s-1] = u0;
                    }
                }
            }
        }
    }
#pragma unroll
    for (int s = 0; s < KKN; s++) out_idx[(size_t)(b*NN + i)*KKN + s] = ti[s];
}

// ---------------- knn for C=64: tf32-MMA Gram tile + insertion ---------------
// CTA: one batch b, one block of 128 query points. 256 threads (8 warps).
// dot tile (128x128) computed on tensor pipe (hi/lo split), selection on rows.
__global__ void __launch_bounds__(256, 1)
knn64_kernel(int* __restrict__ out_idx) {
    extern __shared__ float sm[];
    constexpr int ASTR = 68, BSTR = 136, DSTR = 133;
    float* XiH = sm;                       // [128][68]
    float* XiL = sm + 128*ASTR;
    float* XjH = sm + 2*128*ASTR;          // [64][136]  (k major, j minor)
    float* XjL = XjH + 64*BSTR;
    float* dist = XjL + 64*BSTR;           // [128][133]
    float* x2j  = dist + 128*DSTR;         // [128]

    int tid = threadIdx.x, wid = tid >> 5, lane = tid & 31;
    int gid = lane >> 2, tig = lane & 3;
    int b  = blockIdx.x >> 5;
    int i0 = (blockIdx.x & 31) * 128;

    int mbase = (wid >> 2) * 64;
    int nbase = (wid & 3) * 32;

    // load Xi block (A operand) + own |xi|^2
    float x2i = 0.f;
    if (tid < 128) {
        const float4* row = (const float4*)&g_x1[(size_t)(b*NN + i0 + tid)*64];
#pragma unroll
        for (int q = 0; q < 16; q++) {
            float4 v = row[q];
            float c4[4] = {v.x, v.y, v.z, v.w};
#pragma unroll
            for (int u = 0; u < 4; u++) {
                float c = c4[u];
                x2i += c*c;
                float hi, lo; tf32_split(c, hi, lo);
                XiH[tid*ASTR + q*4 + u] = hi;
                XiL[tid*ASTR + q*4 + u] = lo;
            }
        }
    }

    float td[KKN]; int ti[KKN];
#pragma unroll
    for (int s = 0; s < KKN; s++) { td[s] = 3.4e38f; ti[s] = 0; }

    for (int jt = 0; jt < 32; jt++) {
        __syncthreads();   // selection of prev tile done before overwriting Xj/x2j
        if (tid < 128) {
            const float4* row = (const float4*)&g_x1[(size_t)(b*NN + jt*128 + tid)*64];
            float s2 = 0.f;
#pragma unroll
            for (int q = 0; q < 16; q++) {
                float4 v = row[q];
                float c4[4] = {v.x, v.y, v.z, v.w};
#pragma unroll
                for (int u = 0; u < 4; u++) {
                    float c = c4[u];
                    s2 += c*c;
                    float hi, lo; tf32_split(c, hi, lo);
                    XjH[(q*4 + u)*BSTR + tid] = hi;
                    XjL[(q*4 + u)*BSTR + tid] = lo;
                }
            }
            x2j[tid] = s2;
        }
        __syncthreads();

        float acc[4][4][4];
#pragma unroll
        for (int mt = 0; mt < 4; mt++)
#pragma unroll
            for (int nt = 0; nt < 4; nt++)
#pragma unroll
                for (int u = 0; u < 4; u++) acc[mt][nt][u] = 0.f;

#pragma unroll
        for (int k8 = 0; k8 < 8; k8++) {
            int k0 = k8*8;
            uint32_t ah[4][4], al[4][4], bh[4][2], bl[4][2];
#pragma unroll
            for (int mt = 0; mt < 4; mt++) {
                int rb = mbase + mt*16 + gid;
                ah[mt][0] = __float_as_uint(XiH[rb*ASTR + k0 + tig]);
                ah[mt][1] = __float_as_uint(XiH[(rb+8)*ASTR + k0 + tig]);
                ah[mt][2] = __float_as_uint(XiH[rb*ASTR + k0 + tig + 4]);
                ah[mt][3] = __float_as_uint(XiH[(rb+8)*ASTR + k0 + tig + 4]);
                al[mt][0] = __float_as_uint(XiL[rb*ASTR + k0 + tig]);
                al[mt][1] = __float_as_uint(XiL[(rb+8)*ASTR + k0 + tig]);
                al[mt][2] = __float_as_uint(XiL[rb*ASTR + k0 + tig + 4]);
                al[mt][3] = __float_as_uint(XiL[(rb+8)*ASTR + k0 + tig + 4]);
            }
#pragma unroll
            for (int nt = 0; nt < 4; nt++) {
                int cb = nbase + nt*8 + gid;
                bh[nt][0] = __float_as_uint(XjH[(k0 + tig)*BSTR + cb]);
                bh[nt][1] = __float_as_uint(XjH[(k0 + tig + 4)*BSTR + cb]);
                bl[nt][0] = __float_as_uint(XjL[(k0 + tig)*BSTR + cb]);
                bl[nt][1] = __float_as_uint(XjL[(k0 + tig + 4)*BSTR + cb]);
            }
#pragma unroll
            for (int mt = 0; mt < 4; mt++)
#pragma unroll
                for (int nt = 0; nt < 4; nt++) {
                    mma8(acc[mt][nt], ah[mt], bh[nt]);
                    mma8(acc[mt][nt], ah[mt], bl[nt]);
                    mma8(acc[mt][nt], al[mt], bh[nt]);
                }
        }
        // write dot tile
#pragma unroll
        for (int mt = 0; mt < 4; mt++)
#pragma unroll
            for (int nt = 0; nt < 4; nt++) {
                int row = mbase + mt*16 + gid;
                int col = nbase + nt*8 + tig*2;
                dist[row*DSTR + col]     = acc[mt][nt][0];
                dist[row*DSTR + col + 1] = acc[mt][nt][1];
                dist[(row+8)*DSTR + col]     = acc[mt][nt][2];
                dist[(row+8)*DSTR + col + 1] = acc[mt][nt][3];
            }
        __syncthreads();
        // selection (ascending j, strict '<': matches top_k tie-breaking)
        if (tid < 128) {
            const float* drow = &dist[tid*DSTR];
            for (int jj = 0; jj < 128; jj++) {
                float d = x2i + x2j[jj] - 2.0f*drow[jj];
                if (d < td[KKN-1]) {
                    td[KKN-1] = d; ti[KKN-1] = jt*128 + jj;
#pragma unroll
                    for (int s = KKN-1; s > 0; s--) {
                        if (td[s] < td[s-1]) {
                            float t0 = td[s]; td[s] = td[s-1]; td[s-1] = t0;
                            int   u0 = ti[s]; ti[s] = ti[s-1]; ti[s-1] = u0;
                        }
                    }
                }
            }
        }
    }
    if (tid < 128) {
#pragma unroll
        for (int s = 0; s < KKN; s++)
            out_idx[(size_t)(b*NN + i0 + tid)*KKN + s] = ti[s];
    }
}

// ---------------- edgeconv1 layer1: msg(8) @ W(8x64) + stats -----------------
__global__ void c1_phase1_kernel(const float* __restrict__ X,
                                 const float* __restrict__ W,
                                 const float* __restrict__ bias) {
    __shared__ float sW[8*64];
    __shared__ float sB[64];
    __shared__ float sS[64], sQ[64];
    int tid = threadIdx.x;
    if (tid < 64) { sB[tid] = bias[tid]; sS[tid] = 0.f; sQ[tid] = 0.f; }
    for (int e = tid; e < 512; e += 256) sW[e] = W[e];
    __syncthreads();

    int r  = blockIdx.x * 256 + tid;
    int bn = r / KKN;
    int b  = bn / NN;
    int j  = g_idx[r];
    float msg[8];
#pragma unroll
    for (int c = 0; c < 4; c++) {
        float xi = X[bn*4 + c];
        float xj = X[(size_t)(b*NN + j)*4 + c];
        msg[c] = xi; msg[4+c] = xj - xi;
    }
    int lane = tid & 31;
    float* orow = &g_h[(size_t)r * 64];
#pragma unroll
    for (int co4 = 0; co4 < 16; co4++) {
        float a[4];
#pragma unroll
        for (int u = 0; u < 4; u++) {
            int co = co4*4 + u;
            float acc = sB[co];
#pragma unroll
            for (int ci = 0; ci < 8; ci++) acc = fmaf(msg[ci], sW[ci*64 + co], acc);
            a[u] = acc;
        }
        *(float4*)&orow[co4*4] = make_float4(a[0], a[1], a[2], a[3]);
#pragma unroll
        for (int u = 0; u < 4; u++) {
            float s = a[u], q = a[u]*a[u];
#pragma unroll
            for (int o = 16; o > 0; o >>= 1) {
                s += __shfl_down_sync(0xffffffffu, s, o);
                q += __shfl_down_sync(0xffffffffu, q, o);
            }
            if (lane == 0) { atomicAdd(&sS[co4*4+u], s); atomicAdd(&sQ[co4*4+u], q); }
        }
    }
    __syncthreads();
    if (tid < 64) {
        atomicAdd(&g_sum[0][tid], (double)sS[tid]);
        atomicAdd(&g_ssq[0][tid], (double)sQ[tid]);
    }
}

// ---------------- finalize BN fold: scale/shift ------------------------------
__global__ void finalize_kernel(int stage, const float* __restrict__ gam,
                                const float* __restrict__ bet, float n, int cout) {
    int c = threadIdx.x;
    if (c < cout) {
        double mean = g_sum[stage][c] / (double)n;
        double var  = g_ssq[stage][c] / (double)n - mean*mean;
        float  s    = gam[c] / sqrtf((float)var + EPSI);
        g_scale[stage][c] = s;
        g_shift[stage][c] = bet[c] - (float)mean * s;
    }
}

// ================= warp-MMA tf32 (3x split) GEMM + fused epilogue ============
// D[128, COUT] = A[128, CIN] @ W[CIN, COUT], A produced per MODE:
//  MODE 0: A = [x_i, x_j - x_i] gathered from g_x1 via g_idx  (edgeconv2 L1)
//  MODE 1: A = relu(g_h * scale + shift)                      (layer2, in-place)
//  MODE 2: A = concat(g_x1, g_x2)                             (classifier L1)
// Epilogue: frags+bias -> smem stage -> per-channel sum/sum^2 + store to g_h.
template<int CIN, int COUT, int MODE>
__global__ void __launch_bounds__(256, 1)
tgemm_kernel(int sstage, int pstage, const float* __restrict__ W,
             const float* __restrict__ bias) {
    extern __shared__ float sm[];
    constexpr int NCH  = CIN / 64;
    constexpr int ASTR = 68;
    constexpr int BSTR = COUT + 8;
    constexpr int MT   = (COUT == 128) ? 4 : 2;   // m16 tiles per warp
    float* Ah = sm;                     // [128][68]
    float* Al = sm + 128*ASTR;
    float* Bh = sm + 2*128*ASTR;        // [64][BSTR]
    float* Bl = Bh + 64*BSTR;
    float* stg = sm;                    // epilogue stage (reuse A region)

    int tid = threadIdx.x, wid = tid >> 5, lane = tid & 31;
    int gid = lane >> 2, tig = lane & 3;
    int r0 = blockIdx.x * 128;

    int mbase = (COUT == 128) ? (wid >> 2) * 64 : (wid >> 1) * 32;
    int nbase = (COUT == 128) ? (wid & 3) * 32  : (wid & 1) * 32;

    float acc[MT][4][4];
#pragma unroll
    for (int mt = 0; mt < MT; mt++)
#pragma unroll
        for (int nt = 0; nt < 4; nt++)
#pragma unroll
            for (int u = 0; u < 4; u++) acc[mt][nt][u] = 0.f;

    for (int c = 0; c < NCH; c++) {
        if (c) __syncthreads();
        // ---- produce A chunk (128 x 64) ----
        for (int e = tid; e < 8192; e += 256) {
            int m = e >> 6, k = e & 63;
            int kc = c*64 + k;
            int r = r0 + m;
            float v;
            if constexpr (MODE == 0) {
                int bn = r / KKN;
                if (kc < 64) {
                    v = g_x1[(size_t)bn*64 + kc];
                } else {
                    int b = bn >> 12;
                    int j = g_idx[r];
                    int f = kc - 64;
                    v = g_x1[((size_t)(b << 12) + j)*64 + f] - g_x1[(size_t)bn*64 + f];
                }
            } else if constexpr (MODE == 1) {
                float h = g_h[(size_t)r*CIN + kc];
                v = fmaxf(fmaf(h, g_scale[pstage][kc], g_shift[pstage][kc]), 0.f);
            } else {
                v = (kc < 64) ? g_x1[(size_t)r*64 + kc]
                              : g_x2[(size_t)r*128 + (kc - 64)];
            }
            float hi, lo; tf32_split(v, hi, lo);
            Ah[m*ASTR + k] = hi;
            Al[m*ASTR + k] = lo;
        }
        // ---- load B chunk (64 x COUT), split on the fly ----
        for (int e = tid; e < 64*COUT; e += 256) {
            int k = e / COUT, n = e % COUT;
            float v = W[(size_t)(c*64 + k)*COUT + n];
            float hi, lo; tf32_split(v, hi, lo);
            Bh[k*BSTR + n] = hi;
            Bl[k*BSTR + n] = lo;
        }
        __syncthreads();
        // ---- compute ----
#pragma unroll
        for (int k8 = 0; k8 < 8; k8++) {
            int k0 = k8*8;
            uint32_t ah[MT][4], al[MT][4], bh[4][2], bl[4][2];
#pragma unroll
            for (int mt = 0; mt < MT; mt++) {
                int rb = mbase + mt*16 + gid;
                ah[mt][0] = __float_as_uint(Ah[rb*ASTR + k0 + tig]);
                ah[mt][1] = __float_as_uint(Ah[(rb+8)*ASTR + k0 + tig]);
                ah[mt][2] = __float_as_uint(Ah[rb*ASTR + k0 + tig + 4]);
                ah[mt][3] = __float_as_uint(Ah[(rb+8)*ASTR + k0 + tig + 4]);
                al[mt][0] = __float_as_uint(Al[rb*ASTR + k0 + tig]);
                al[mt][1] = __float_as_uint(Al[(rb+8)*ASTR + k0 + tig]);
                al[mt][2] = __float_as_uint(Al[rb*ASTR + k0 + tig + 4]);
                al[mt][3] = __float_as_uint(Al[(rb+8)*ASTR + k0 + tig + 4]);
            }
#pragma unroll
            for (int nt = 0; nt < 4; nt++) {
                int cb = nbase + nt*8 + gid;
                bh[nt][0] = __float_as_uint(Bh[(k0 + tig)*BSTR + cb]);
                bh[nt][1] = __float_as_uint(Bh[(k0 + tig + 4)*BSTR + cb]);
                bl[nt][0] = __float_as_uint(Bl[(k0 + tig)*BSTR + cb]);
                bl[nt][1] = __float_as_uint(Bl[(k0 + tig + 4)*BSTR + cb]);
            }
#pragma unroll
            for (int mt = 0; mt < MT; mt++)
#pragma unroll
                for (int nt = 0; nt < 4; nt++) {
                    mma8(acc[mt][nt], ah[mt], bh[nt]);
                    mma8(acc[mt][nt], ah[mt], bl[nt]);
                    mma8(acc[mt][nt], al[mt], bh[nt]);
                }
        }
    }
    __syncthreads();
    // ---- epilogue: frags + bias -> stage ----
#pragma unroll
    for (int mt = 0; mt < MT; mt++)
#pragma unroll
        for (int nt = 0; nt < 4; nt++) {
            int row = mbase + mt*16 + gid;
            int col = nbase + nt*8 + tig*2;
            float b0 = bias[col], b1 = bias[col+1];
            stg[row*(COUT+1) + col]       = acc[mt][nt][0] + b0;
            stg[row*(COUT+1) + col + 1]   = acc[mt][nt][1] + b1;
            stg[(row+8)*(COUT+1) + col]     = acc[mt][nt][2] + b0;
            stg[(row+8)*(COUT+1) + col + 1] = acc[mt][nt][3] + b1;
        }
    __syncthreads();
    // ---- per-channel stats ----
    if (tid < COUT) {
        float s = 0.f, q = 0.f;
#pragma unroll 8
        for (int r = 0; r < 128; r++) {
            float v = stg[r*(COUT+1) + tid];
            s += v; q += v*v;
        }
        atomicAdd(&g_sum[sstage][tid], (double)s);
        atomicAdd(&g_ssq[sstage][tid], (double)q);
    }
    // ---- coalesced store to g_h ----
    for (int e = tid; e < 128*(COUT/4); e += 256) {
        int r = e / (COUT/4), c4 = e % (COUT/4);
        const float* p = &stg[r*(COUT+1) + c4*4];
        float4 v = make_float4(p[0], p[1], p[2], p[3]);
        *(float4*)&g_h[(size_t)(r0 + r)*COUT + c4*4] = v;
    }
}

// ---------------- BN+relu + max over k --------------------------------------
template<int COUT>
__global__ void maxpool_kernel(int pstage) {
    int t = blockIdx.x * 256 + threadIdx.x;
    int c  = t & (COUT - 1);
    int bn = t >> (COUT == 64 ? 6 : 7);
    float s  = g_scale[pstage][c], sh = g_shift[pstage][c];
    const float* base = &g_h[((size_t)bn * KKN) * COUT + c];
    float m = -3.4e38f;
#pragma unroll
    for (int kk = 0; kk < KKN; kk++)
        m = fmaxf(m, fmaf(base[(size_t)kk*COUT], s, sh));
    m = fmaxf(m, 0.f);
    if (COUT == 64) g_x1[t] = m; else g_x2[t] = m;
}

// ---------------- classifier final: relu(bn(h)) @ w2 + b2 -------------------
__global__ void cls_final_kernel(const float* __restrict__ W2,
                                 const float* __restrict__ B2,
                                 float* __restrict__ out) {
    int gw   = (blockIdx.x * blockDim.x + threadIdx.x) >> 5;
    int lane = threadIdx.x & 31;
    const float* hrow = &g_h[(size_t)gw * 128];
    float p = 0.f;
#pragma unroll
    for (int q = 0; q < 4; q++) {
        int c = lane + 32*q;
        float v = fmaxf(fmaf(hrow[c], g_scale[4][c], g_shift[4][c]), 0.f);
        p = fmaf(v, W2[c], p);
    }
#pragma unroll
    for (int o = 16; o > 0; o >>= 1) p += __shfl_down_sync(0xffffffffu, p, o);
    if (lane == 0) out[gw] = p + B2[0];
}

// ---------------- host orchestration ----------------------------------------
extern "C" void kernel_launch(void* const* d_in, const int* in_sizes, int n_in,
                              void* d_out, int out_size) {
    const float* x      = (const float*)d_in[0];
    const float* c1_w1  = (const float*)d_in[1];
    const float* c1_b1  = (const float*)d_in[2];
    const float* c1_g1  = (const float*)d_in[3];
    const float* c1_be1 = (const float*)d_in[4];
    const float* c1_w2  = (const float*)d_in[5];
    const float* c1_b2  = (const float*)d_in[6];
    const float* c1_g2  = (const float*)d_in[7];
    const float* c1_be2 = (const float*)d_in[8];
    const float* c2_w1  = (const float*)d_in[9];
    const float* c2_b1  = (const float*)d_in[10];
    const float* c2_g1  = (const float*)d_in[11];
    const float* c2_be1 = (const float*)d_in[12];
    const float* c2_w2  = (const float*)d_in[13];
    const float* c2_b2  = (const float*)d_in[14];
    const float* c2_g2  = (const float*)d_in[15];
    const float* c2_be2 = (const float*)d_in[16];
    const float* cls_w1 = (const float*)d_in[17];
    const float* cls_b1 = (const float*)d_in[18];
    const float* cls_g1 = (const float*)d_in[19];
    const float* cls_be1= (const float*)d_in[20];
    const float* cls_w2 = (const float*)d_in[21];
    const float* cls_b2 = (const float*)d_in[22];
    float* out = (float*)d_out;

    int* idx_ptr;
    cudaGetSymbolAddress((void**)&idx_ptr, g_idx);

    const int SMB128 = (2*128*68 + 2*64*136) * 4;          // 139264
    const int SMB64  = (2*128*68 + 2*64*72) * 4;           // 106496
    const int SMKNN  = (2*128*68 + 2*64*136 + 128*133 + 128) * 4;  // 207872
    cudaFuncSetAttribute(tgemm_kernel<64,64,1>,   cudaFuncAttributeMaxDynamicSharedMemorySize, SMB64);
    cudaFuncSetAttribute(tgemm_kernel<128,128,0>, cudaFuncAttributeMaxDynamicSharedMemorySize, SMB128);
    cudaFuncSetAttribute(tgemm_kernel<128,128,1>, cudaFuncAttributeMaxDynamicSharedMemorySize, SMB128);
    cudaFuncSetAttribute(tgemm_kernel<192,128,2>, cudaFuncAttributeMaxDynamicSharedMemorySize, SMB128);
    cudaFuncSetAttribute(knn64_kernel,            cudaFuncAttributeMaxDynamicSharedMemorySize, SMKNN);

    zero_stats_kernel<<<3, 256>>>();

    // ---- EdgeConv 1 ----
    knn4_kernel<<<BB*(NN/128), 128>>>(x, idx_ptr);
    c1_phase1_kernel<<<R_EDGE/256, 256>>>(x, c1_w1, c1_b1);
    finalize_kernel<<<1, 128>>>(0, c1_g1, c1_be1, (float)R_EDGE, 64);
    tgemm_kernel<64,64,1><<<R_EDGE/128, 256, SMB64>>>(1, 0, c1_w2, c1_b2);
    finalize_kernel<<<1, 128>>>(1, c1_g2, c1_be2, (float)R_EDGE, 64);
    maxpool_kernel<64><<<BN_TOTAL*64/256, 256>>>(1);

    // ---- EdgeConv 2 ----
    knn64_kernel<<<BB*32, 256, SMKNN>>>(idx_ptr);
    tgemm_kernel<128,128,0><<<R_EDGE/128, 256, SMB128>>>(2, 0, c2_w1, c2_b1);
    finalize_kernel<<<1, 128>>>(2, c2_g1, c2_be1, (float)R_EDGE, 128);
    tgemm_kernel<128,128,1><<<R_EDGE/128, 256, SMB128>>>(3, 2, c2_w2, c2_b2);
    finalize_kernel<<<1, 128>>>(3, c2_g2, c2_be2, (float)R_EDGE, 128);
    maxpool_kernel<128><<<BN_TOTAL*128/256, 256>>>(3);

    // ---- Classifier ----
    tgemm_kernel<192,128,2><<<BN_TOTAL/128, 256, SMB128>>>(4, 0, cls_w1, cls_b1);
    finalize_kernel<<<1, 128>>>(4, cls_g1, cls_be1, (float)BN_TOTAL, 128);
    cls_final_kernel<<<BN_TOTAL/8, 256>>>(cls_w2, cls_b2, out);
}

// round 4
// speedup vs baseline: 1.3492x; 1.3254x over previous
#include <cuda_runtime.h>
#include <cuda_fp16.h>
#include <math.h>
#include <stdint.h>

#define BB 8
#define NN 4096
#define KKN 20
#define BN_TOTAL (BB*NN)          // 32768
#define R_EDGE (BB*NN*KKN)        // 655360
#define EPSI 1e-5f

// ---------------- scratch (device globals; no allocation allowed) ------------
__device__ float  g_h[(size_t)R_EDGE*128];  // activation scratch
__device__ float  g_x1[BN_TOTAL*64];        // edgeconv1 output
__device__ float  g_x2[BN_TOTAL*128];       // edgeconv2 output
__device__ int    g_idx[R_EDGE];            // knn indices (reused per stage)
__device__ double g_sum[5][128];
__device__ double g_ssq[5][128];

// ---------------- helpers -----------------------------------------------------
__device__ __forceinline__ uint32_t hpack(float v0, float v1, float& r0, float& r1) {
    __half h0 = __float2half_rn(v0), h1 = __float2half_rn(v1);
    r0 = v0 - __half2float(h0);
    r1 = v1 - __half2float(h1);
    __half2 p = __halves2half2(h0, h1);
    return *(uint32_t*)&p;
}
__device__ __forceinline__ uint32_t hpack2(float v0, float v1) {
    __half2 p = __halves2half2(__float2half_rn(v0), __float2half_rn(v1));
    return *(uint32_t*)&p;
}
// D += A(16x16) * B(16x8), fp16 in, f32 accum
__device__ __forceinline__ void mma16(float* c, const uint32_t* a, const uint32_t* b) {
    asm volatile("mma.sync.aligned.m16n8k16.row.col.f32.f16.f16.f32 "
        "{%0,%1,%2,%3}, {%4,%5,%6,%7}, {%8,%9}, {%0,%1,%2,%3};"
        : "+f"(c[0]), "+f"(c[1]), "+f"(c[2]), "+f"(c[3])
        : "r"(a[0]), "r"(a[1]), "r"(a[2]), "r"(a[3]), "r"(b[0]), "r"(b[1]));
}
// per-CTA BN affine from global double stats (replaces finalize_kernel)
__device__ __forceinline__ void affine_init(int stage, const float* gam, const float* bet,
                                            float n, int cout, float* sSc, float* sSh, int tid) {
    if (tid < cout) {
        double mean = g_sum[stage][tid] / (double)n;
        double var  = g_ssq[stage][tid] / (double)n - mean*mean;
        float  s    = gam[tid] / sqrtf((float)var + EPSI);
        sSc[tid] = s;
        sSh[tid] = bet[tid] - (float)mean * s;
    }
}

// ---------------- knn for C=4 (+ stats zeroing) -------------------------------
__global__ void knn4_kernel(const float* __restrict__ Xin, int* __restrict__ out_idx) {
    constexpr int TI = 128, TJ = 128;
    __shared__ float4 sxj[TJ];
    __shared__ float  sx2[TJ];
    const float4* X4 = (const float4*)Xin;

    if (blockIdx.x == 0) {   // zero BN stats for all 5 stages
        for (int t = threadIdx.x; t < 640; t += TI) {
            (&g_sum[0][0])[t] = 0.0; (&g_ssq[0][0])[t] = 0.0;
        }
    }

    int b = blockIdx.x / (NN / TI);
    int i = (blockIdx.x % (NN / TI)) * TI + threadIdx.x;

    float4 xi = X4[(size_t)b*NN + i];
    float x2i = xi.x*xi.x + xi.y*xi.y + xi.z*xi.z + xi.w*xi.w;

    float td[KKN]; int ti[KKN];
#pragma unroll
    for (int s = 0; s < KKN; s++) { td[s] = 3.4e38f; ti[s] = 0; }

    for (int j0 = 0; j0 < NN; j0 += TJ) {
        __syncthreads();
        {
            float4 v = X4[(size_t)b*NN + j0 + threadIdx.x];
            sxj[threadIdx.x] = v;
            sx2[threadIdx.x] = v.x*v.x + v.y*v.y + v.z*v.z + v.w*v.w;
        }
        __syncthreads();
        for (int jj = 0; jj < TJ; jj++) {
            float4 v = sxj[jj];
            float dot = xi.x*v.x + xi.y*v.y + xi.z*v.z + xi.w*v.w;
            float d = x2i + sx2[jj] - 2.0f*dot;
            if (d < td[KKN-1]) {
                td[KKN-1] = d; ti[KKN-1] = j0 + jj;
#pragma unroll
                for (int s = KKN-1; s > 0; s--) {
                    if (td[s] < td[s-1]) {
                        float t0 = td[s]; td[s] = td[s-1]; td[s-1] = t0;
                        int   u0 = ti[s]; ti[s] = ti[s-1]; ti[s-1] = u0;
                    }
                }
            }
        }
    }
#pragma unroll
    for (int s = 0; s < KKN; s++) out_idx[(size_t)(b*NN + i)*KKN + s] = ti[s];
}

// ---------------- knn for C=64: fp16-split MMA Gram + insertion ---------------
// smem (half2/float units): XiH[128][36], XiL[128][36], XjH[32][136], XjL[32][136],
// dist[128][133] (float), x2j[128]
__global__ void __launch_bounds__(256, 1)
knn64_kernel(int* __restrict__ out_idx) {
    extern __shared__ uint32_t smu[];
    constexpr int AS = 36, BS = 136;
    uint32_t* XiH = smu;                    // packed half2
    uint32_t* XiL = smu + 128*AS;
    uint32_t* XjH = smu + 2*128*AS;
    uint32_t* XjL = XjH + 32*BS;
    float* dist = (float*)(XjL + 32*BS);
    float* x2j  = dist + 128*133;

    int tid = threadIdx.x, wid = tid >> 5, lane = tid & 31;
    int gid = lane >> 2, tig = lane & 3;
    int b  = blockIdx.x >> 5;
    int i0 = (blockIdx.x & 31) * 128;

    int mbase = (wid >> 2) * 64;
    int nbase = (wid & 3) * 32;

    float x2i = 0.f;
    if (tid < 128) {
        const float4* row = (const float4*)&g_x1[(size_t)(b*NN + i0 + tid)*64];
#pragma unroll
        for (int q = 0; q < 16; q++) {
            float4 v = row[q];
            x2i += v.x*v.x + v.y*v.y + v.z*v.z + v.w*v.w;
            float r0, r1;
            XiH[tid*AS + 2*q]   = hpack(v.x, v.y, r0, r1);
            XiL[tid*AS + 2*q]   = hpack2(r0, r1);
            XiH[tid*AS + 2*q+1] = hpack(v.z, v.w, r0, r1);
            XiL[tid*AS + 2*q+1] = hpack2(r0, r1);
        }
    }

    float td[KKN]; int ti[KKN];
#pragma unroll
    for (int s = 0; s < KKN; s++) { td[s] = 3.4e38f; ti[s] = 0; }

    for (int jt = 0; jt < 32; jt++) {
        __syncthreads();
        if (tid < 128) {
            const float4* row = (const float4*)&g_x1[(size_t)(b*NN + jt*128 + tid)*64];
            float s2 = 0.f;
#pragma unroll
            for (int q = 0; q < 16; q++) {
                float4 v = row[q];
                s2 += v.x*v.x + v.y*v.y + v.z*v.z + v.w*v.w;
                float r0, r1;
                XjH[(2*q)*BS + tid]   = hpack(v.x, v.y, r0, r1);
                XjL[(2*q)*BS + tid]   = hpack2(r0, r1);
                XjH[(2*q+1)*BS + tid] = hpack(v.z, v.w, r0, r1);
                XjL[(2*q+1)*BS + tid] = hpack2(r0, r1);
            }
            x2j[tid] = s2;
        }
        __syncthreads();

        float acc[4][4][4];
#pragma unroll
        for (int mt = 0; mt < 4; mt++)
#pragma unroll
            for (int nt = 0; nt < 4; nt++)
#pragma unroll
                for (int u = 0; u < 4; u++) acc[mt][nt][u] = 0.f;

#pragma unroll
        for (int kk = 0; kk < 4; kk++) {
            int k2b = kk*8;
            uint32_t ah[4][4], al[4][4], bh[4][2], bl[4][2];
#pragma unroll
            for (int mt = 0; mt < 4; mt++) {
                int rb = mbase + mt*16 + gid;
                ah[mt][0] = XiH[rb*AS + k2b + tig];
                ah[mt][1] = XiH[(rb+8)*AS + k2b + tig];
                ah[mt][2] = XiH[rb*AS + k2b + tig + 4];
                ah[mt][3] = XiH[(rb+8)*AS + k2b + tig + 4];
                al[mt][0] = XiL[rb*AS + k2b + tig];
                al[mt][1] = XiL[(rb+8)*AS + k2b + tig];
                al[mt][2] = XiL[rb*AS + k2b + tig + 4];
                al[mt][3] = XiL[(rb+8)*AS + k2b + tig + 4];
            }
#pragma unroll
            for (int nt = 0; nt < 4; nt++) {
                int cb = nbase + nt*8 + gid;
                bh[nt][0] = XjH[(k2b + tig)*BS + cb];
                bh[nt][1] = XjH[(k2b + tig + 4)*BS + cb];
                bl[nt][0] = XjL[(k2b + tig)*BS + cb];
                bl[nt][1] = XjL[(k2b + tig + 4)*BS + cb];
            }
#pragma unroll
            for (int mt = 0; mt < 4; mt++)
#pragma unroll
                for (int nt = 0; nt < 4; nt++) {
                    mma16(acc[mt][nt], ah[mt], bh[nt]);
                    mma16(acc[mt][nt], ah[mt], bl[nt]);
                    mma16(acc[mt][nt], al[mt], bh[nt]);
                }
        }
#pragma unroll
        for (int mt = 0; mt < 4; mt++)
#pragma unroll
            for (int nt = 0; nt < 4; nt++) {
                int row = mbase + mt*16 + gid;
                int col = nbase + nt*8 + tig*2;
                dist[row*133 + col]       = acc[mt][nt][0];
                dist[row*133 + col + 1]   = acc[mt][nt][1];
                dist[(row+8)*133 + col]     = acc[mt][nt][2];
                dist[(row+8)*133 + col + 1] = acc[mt][nt][3];
            }
        __syncthreads();
        if (tid < 128) {
            const float* drow = &dist[tid*133];
            for (int jj = 0; jj < 128; jj++) {
                float d = x2i + x2j[jj] - 2.0f*drow[jj];
                if (d < td[KKN-1]) {
                    td[KKN-1] = d; ti[KKN-1] = jt*128 + jj;
#pragma unroll
                    for (int s = KKN-1; s > 0; s--) {
                        if (td[s] < td[s-1]) {
                            float t0 = td[s]; td[s] = td[s-1]; td[s-1] = t0;
                            int   u0 = ti[s]; ti[s] = ti[s-1]; ti[s-1] = u0;
                        }
                    }
                }
            }
        }
    }
    if (tid < 128) {
#pragma unroll
        for (int s = 0; s < KKN; s++)
            out_idx[(size_t)(b*NN + i0 + tid)*KKN + s] = ti[s];
    }
}

// ---------------- edgeconv1 layer1: msg(8) @ W(8x64) + stats -----------------
__global__ void c1_phase1_kernel(const float* __restrict__ X,
                                 const float* __restrict__ W,
                                 const float* __restrict__ bias) {
    __shared__ float sW[8*64];
    __shared__ float sB[64];
    __shared__ float sS[64], sQ[64];
    int tid = threadIdx.x;
    if (tid < 64) { sB[tid] = bias[tid]; sS[tid] = 0.f; sQ[tid] = 0.f; }
    for (int e = tid; e < 512; e += 256) sW[e] = W[e];
    __syncthreads();

    int r  = blockIdx.x * 256 + tid;
    int bn = r / KKN;
    int b  = bn / NN;
    int j  = g_idx[r];
    float msg[8];
#pragma unroll
    for (int c = 0; c < 4; c++) {
        float xi = X[bn*4 + c];
        float xj = X[(size_t)(b*NN + j)*4 + c];
        msg[c] = xi; msg[4+c] = xj - xi;
    }
    int lane = tid & 31;
    float* orow = &g_h[(size_t)r * 64];
#pragma unroll
    for (int co4 = 0; co4 < 16; co4++) {
        float a[4];
#pragma unroll
        for (int u = 0; u < 4; u++) {
            int co = co4*4 + u;
            float acc = sB[co];
#pragma unroll
            for (int ci = 0; ci < 8; ci++) acc = fmaf(msg[ci], sW[ci*64 + co], acc);
            a[u] = acc;
        }
        *(float4*)&orow[co4*4] = make_float4(a[0], a[1], a[2], a[3]);
#pragma unroll
        for (int u = 0; u < 4; u++) {
            float s = a[u], q = a[u]*a[u];
#pragma unroll
            for (int o = 16; o > 0; o >>= 1) {
                s += __shfl_down_sync(0xffffffffu, s, o);
                q += __shfl_down_sync(0xffffffffu, q, o);
            }
            if (lane == 0) { atomicAdd(&sS[co4*4+u], s); atomicAdd(&sQ[co4*4+u], q); }
        }
    }
    __syncthreads();
    if (tid < 64) {
        atomicAdd(&g_sum[0][tid], (double)sS[tid]);
        atomicAdd(&g_ssq[0][tid], (double)sQ[tid]);
    }
}

// ================= fp16-split warp-MMA GEMM + fused epilogue =================
// MODE 0: A = [x_i, x_j - x_i] gathered; MODE 1: A = relu(bn(g_h)); MODE 2: concat.
template<int CIN, int COUT, int MODE>
__global__ void __launch_bounds__(256, 2)
tgemm_kernel(int sstage, int pstage, const float* __restrict__ W,
             const float* __restrict__ bias,
             const float* __restrict__ gam, const float* __restrict__ bet, float nstat) {
    extern __shared__ uint32_t smu[];
    constexpr int NCH = CIN / 64;
    constexpr int AS  = 36;            // half2 stride (4g+t banks)
    constexpr int BS  = COUT + 8;      // half2 stride (8t+g banks)
    constexpr int MT  = (COUT == 128) ? 4 : 2;
    uint32_t* Ah = smu;                // [128][36]
    uint32_t* Al = smu + 128*AS;
    uint32_t* Bh = smu + 2*128*AS;     // [32][BS]
    uint32_t* Bl = Bh + 32*BS;
    float* stg = (float*)smu;          // epilogue stage (reuse)
    __shared__ float sSc[128], sSh[128];

    int tid = threadIdx.x, wid = tid >> 5, lane = tid & 31;
    int gid = lane >> 2, tig = lane & 3;
    int r0 = blockIdx.x * 128;

    if constexpr (MODE == 1) {
        affine_init(pstage, gam, bet, nstat, CIN, sSc, sSh, tid);
        __syncthreads();
    }

    int mbase = (COUT == 128) ? (wid >> 2) * 64 : (wid >> 1) * 32;
    int nbase = (COUT == 128) ? (wid & 3) * 32  : (wid & 1) * 32;

    float acc[MT][4][4];
#pragma unroll
    for (int mt = 0; mt < MT; mt++)
#pragma unroll
        for (int nt = 0; nt < 4; nt++)
#pragma unroll
            for (int u = 0; u < 4; u++) acc[mt][nt][u] = 0.f;

    for (int c = 0; c < NCH; c++) {
        if (c) __syncthreads();
        // ---- produce A chunk (128 rows x 32 half2-pairs) ----
        for (int e2 = tid; e2 < 128*32; e2 += 256) {
            int m = e2 >> 5, k2 = e2 & 31;
            int kc = c*64 + k2*2;
            int r = r0 + m;
            float v0, v1;
            if constexpr (MODE == 0) {
                int bn = r / KKN;
                if (kc < 64) {
                    float2 p = *(const float2*)&g_x1[(size_t)bn*64 + kc];
                    v0 = p.x; v1 = p.y;
                } else {
                    int b = bn >> 12;
                    int j = g_idx[r];
                    int f = kc - 64;
                    float2 pj = *(const float2*)&g_x1[((size_t)(b << 12) + j)*64 + f];
                    float2 pi = *(const float2*)&g_x1[(size_t)bn*64 + f];
                    v0 = pj.x - pi.x; v1 = pj.y - pi.y;
                }
            } else if constexpr (MODE == 1) {
                float2 p = *(const float2*)&g_h[(size_t)r*CIN + kc];
                v0 = fmaxf(fmaf(p.x, sSc[kc],   sSh[kc]),   0.f);
                v1 = fmaxf(fmaf(p.y, sSc[kc+1], sSh[kc+1]), 0.f);
            } else {
                if (kc < 64) {
                    float2 p = *(const float2*)&g_x1[(size_t)r*64 + kc];
                    v0 = p.x; v1 = p.y;
                } else {
                    float2 p = *(const float2*)&g_x2[(size_t)r*128 + (kc - 64)];
                    v0 = p.x; v1 = p.y;
                }
            }
            float r0f, r1f;
            Ah[m*AS + k2] = hpack(v0, v1, r0f, r1f);
            Al[m*AS + k2] = hpack2(r0f, r1f);
        }
        // ---- produce B chunk (32 k2 x COUT) ----
        for (int e2 = tid; e2 < 32*COUT; e2 += 256) {
            int k2 = e2 / COUT, n = e2 % COUT;
            float w0 = W[(size_t)(c*64 + 2*k2)*COUT + n];
            float w1 = W[(size_t)(c*64 + 2*k2 + 1)*COUT + n];
            float r0f, r1f;
            Bh[k2*BS + n] = hpack(w0, w1, r0f, r1f);
            Bl[k2*BS + n] = hpack2(r0f, r1f);
        }
        __syncthreads();
        // ---- compute: 4 k16 steps ----
#pragma unroll
        for (int kk = 0; kk < 4; kk++) {
            int k2b = kk*8;
            uint32_t ah[MT][4], al[MT][4], bh[4][2], bl[4][2];
#pragma unroll
            for (int mt = 0; mt < MT; mt++) {
                int rb = mbase + mt*16 + gid;
                ah[mt][0] = Ah[rb*AS + k2b + tig];
                ah[mt][1] = Ah[(rb+8)*AS + k2b + tig];
                ah[mt][2] = Ah[rb*AS + k2b + tig + 4];
                ah[mt][3] = Ah[(rb+8)*AS + k2b + tig + 4];
                al[mt][0] = Al[rb*AS + k2b + tig];
                al[mt][1] = Al[(rb+8)*AS + k2b + tig];
                al[mt][2] = Al[rb*AS + k2b + tig + 4];
                al[mt][3] = Al[(rb+8)*AS + k2b + tig + 4];
            }
#pragma unroll
            for (int nt = 0; nt < 4; nt++) {
                int cb = nbase + nt*8 + gid;
                bh[nt][0] = Bh[(k2b + tig)*BS + cb];
                bh[nt][1] = Bh[(k2b + tig + 4)*BS + cb];
                bl[nt][0] = Bl[(k2b + tig)*BS + cb];
                bl[nt][1] = Bl[(k2b + tig + 4)*BS + cb];
            }
#pragma unroll
            for (int mt = 0; mt < MT; mt++)
#pragma unroll
                for (int nt = 0; nt < 4; nt++) {
                    mma16(acc[mt][nt], ah[mt], bh[nt]);
                    mma16(acc[mt][nt], ah[mt], bl[nt]);
                    mma16(acc[mt][nt], al[mt], bh[nt]);
                }
        }
    }
    __syncthreads();
    // ---- epilogue: frags + bias -> stage ----
#pragma unroll
    for (int mt = 0; mt < MT; mt++)
#pragma unroll
        for (int nt = 0; nt < 4; nt++) {
            int row = mbase + mt*16 + gid;
            int col = nbase + nt*8 + tig*2;
            float b0 = bias[col], b1 = bias[col+1];
            stg[row*(COUT+1) + col]         = acc[mt][nt][0] + b0;
            stg[row*(COUT+1) + col + 1]     = acc[mt][nt][1] + b1;
            stg[(row+8)*(COUT+1) + col]     = acc[mt][nt][2] + b0;
            stg[(row+8)*(COUT+1) + col + 1] = acc[mt][nt][3] + b1;
        }
    __syncthreads();
    // ---- per-channel stats ----
    if (tid < COUT) {
        float s = 0.f, q = 0.f;
#pragma unroll 8
        for (int r = 0; r < 128; r++) {
            float v = stg[r*(COUT+1) + tid];
            s += v; q += v*v;
        }
        atomicAdd(&g_sum[sstage][tid], (double)s);
        atomicAdd(&g_ssq[sstage][tid], (double)q);
    }
    // ---- coalesced store to g_h ----
    for (int e = tid; e < 128*(COUT/4); e += 256) {
        int r = e / (COUT/4), c4 = e % (COUT/4);
        const float* p = &stg[r*(COUT+1) + c4*4];
        float4 v = make_float4(p[0], p[1], p[2], p[3]);
        *(float4*)&g_h[(size_t)(r0 + r)*COUT + c4*4] = v;
    }
}

// ---------------- BN+relu + max over k --------------------------------------
template<int COUT>
__global__ void maxpool_kernel(int pstage, const float* __restrict__ gam,
                               const float* __restrict__ bet, float nstat) {
    __shared__ float sSc[COUT], sSh[COUT];
    affine_init(pstage, gam, bet, nstat, COUT, sSc, sSh, threadIdx.x);
    __syncthreads();
    int t = blockIdx.x * 256 + threadIdx.x;
    int c  = t & (COUT - 1);
    int bn = t >> (COUT == 64 ? 6 : 7);
    float s  = sSc[c], sh = sSh[c];
    const float* base = &g_h[((size_t)bn * KKN) * COUT + c];
    float m = -3.4e38f;
#pragma unroll
    for (int kk = 0; kk < KKN; kk++)
        m = fmaxf(m, fmaf(base[(size_t)kk*COUT], s, sh));
    m = fmaxf(m, 0.f);
    if (COUT == 64) g_x1[t] = m; else g_x2[t] = m;
}

// ---------------- classifier final: relu(bn(h)) @ w2 + b2 -------------------
__global__ void cls_final_kernel(const float* __restrict__ W2,
                                 const float* __restrict__ B2,
                                 const float* __restrict__ gam,
                                 const float* __restrict__ bet,
                                 float* __restrict__ out) {
    __shared__ float sSc[128], sSh[128];
    affine_init(4, gam, bet, (float)BN_TOTAL, 128, sSc, sSh, threadIdx.x);
    __syncthreads();
    int gw   = (blockIdx.x * blockDim.x + threadIdx.x) >> 5;
    int lane = threadIdx.x & 31;
    const float* hrow = &g_h[(size_t)gw * 128];
    float p = 0.f;
#pragma unroll
    for (int q = 0; q < 4; q++) {
        int c = lane + 32*q;
        float v = fmaxf(fmaf(hrow[c], sSc[c], sSh[c]), 0.f);
        p = fmaf(v, W2[c], p);
    }
#pragma unroll
    for (int o = 16; o > 0; o >>= 1) p += __shfl_down_sync(0xffffffffu, p, o);
    if (lane == 0) out[gw] = p + B2[0];
}

// ---------------- host orchestration ----------------------------------------
extern "C" void kernel_launch(void* const* d_in, const int* in_sizes, int n_in,
                              void* d_out, int out_size) {
    const float* x      = (const float*)d_in[0];
    const float* c1_w1  = (const float*)d_in[1];
    const float* c1_b1  = (const float*)d_in[2];
    const float* c1_g1  = (const float*)d_in[3];
    const float* c1_be1 = (const float*)d_in[4];
    const float* c1_w2  = (const float*)d_in[5];
    const float* c1_b2  = (const float*)d_in[6];
    const float* c1_g2  = (const float*)d_in[7];
    const float* c1_be2 = (const float*)d_in[8];
    const float* c2_w1  = (const float*)d_in[9];
    const float* c2_b1  = (const float*)d_in[10];
    const float* c2_g1  = (const float*)d_in[11];
    const float* c2_be1 = (const float*)d_in[12];
    const float* c2_w2  = (const float*)d_in[13];
    const float* c2_b2  = (const float*)d_in[14];
    const float* c2_g2  = (const float*)d_in[15];
    const float* c2_be2 = (const float*)d_in[16];
    const float* cls_w1 = (const float*)d_in[17];
    const float* cls_b1 = (const float*)d_in[18];
    const float* cls_g1 = (const float*)d_in[19];
    const float* cls_be1= (const float*)d_in[20];
    const float* cls_w2 = (const float*)d_in[21];
    const float* cls_b2 = (const float*)d_in[22];
    float* out = (float*)d_out;

    int* idx_ptr;
    cudaGetSymbolAddress((void**)&idx_ptr, g_idx);

    const int SMB128 = (2*128*36 + 2*32*136) * 4;                    // 71680
    const int SMB64  = (2*128*36 + 2*32*72)  * 4;                    // 55296
    const int SMKNN  = (2*128*36 + 2*32*136 + 128*133 + 128) * 4;    // 140288
    cudaFuncSetAttribute(tgemm_kernel<64,64,1>,   cudaFuncAttributeMaxDynamicSharedMemorySize, SMB64);
    cudaFuncSetAttribute(tgemm_kernel<128,128,0>, cudaFuncAttributeMaxDynamicSharedMemorySize, SMB128);
    cudaFuncSetAttribute(tgemm_kernel<128,128,1>, cudaFuncAttributeMaxDynamicSharedMemorySize, SMB128);
    cudaFuncSetAttribute(tgemm_kernel<192,128,2>, cudaFuncAttributeMaxDynamicSharedMemorySize, SMB128);
    cudaFuncSetAttribute(knn64_kernel,            cudaFuncAttributeMaxDynamicSharedMemorySize, SMKNN);

    // launch order chosen so ncu (-s 5 -c 1) captures launch #6 = big MODE-0 GEMM
    knn4_kernel<<<BB*(NN/128), 128>>>(x, idx_ptr);                                   // 1
    c1_phase1_kernel<<<R_EDGE/256, 256>>>(x, c1_w1, c1_b1);                          // 2
    tgemm_kernel<64,64,1><<<R_EDGE/128, 256, SMB64>>>(1, 0, c1_w2, c1_b2,
                                                      c1_g1, c1_be1, (float)R_EDGE); // 3
    maxpool_kernel<64><<<BN_TOTAL*64/256, 256>>>(1, c1_g2, c1_be2, (float)R_EDGE);   // 4
    knn64_kernel<<<BB*32, 256, SMKNN>>>(idx_ptr);                                    // 5
    tgemm_kernel<128,128,0><<<R_EDGE/128, 256, SMB128>>>(2, 0, c2_w1, c2_b1,
                                                      c1_g1, c1_be1, (float)R_EDGE); // 6 <- ncu
    tgemm_kernel<128,128,1><<<R_EDGE/128, 256, SMB128>>>(3, 2, c2_w2, c2_b2,
                                                      c2_g1, c2_be1, (float)R_EDGE); // 7
    maxpool_kernel<128><<<BN_TOTAL*128/256, 256>>>(3, c2_g2, c2_be2, (float)R_EDGE); // 8
    tgemm_kernel<192,128,2><<<BN_TOTAL/128, 256, SMB128>>>(4, 0, cls_w1, cls_b1,
                                                      c1_g1, c1_be1, (float)R_EDGE); // 9
    cls_final_kernel<<<BN_TOTAL/8, 256>>>(cls_w2, cls_b2, cls_g1, cls_be1, out);     // 10
}

// round 6
// speedup vs baseline: 1.4882x; 1.1030x over previous
#include <cuda_runtime.h>
#include <cuda_fp16.h>
#include <math.h>
#include <stdint.h>

#define BB 8
#define NN 4096
#define KKN 20
#define BN_TOTAL (BB*NN)          // 32768
#define R_EDGE (BB*NN*KKN)        // 655360
#define EPSI 1e-5f

// ---------------- scratch (device globals; no allocation allowed) ------------
__device__ float  g_h[(size_t)R_EDGE*128];  // layer-2 activation scratch
__device__ float  g_x1[BN_TOTAL*64];        // edgeconv1 output
__device__ float  g_x2[BN_TOTAL*128];       // edgeconv2 output
__device__ float  g_P1[BN_TOTAL*64],  g_Q1[BN_TOTAL*64];
__device__ float  g_P2[BN_TOTAL*128], g_Q2[BN_TOTAL*128];
__device__ int    g_idx[R_EDGE];
__device__ double g_sum[5][128];
__device__ double g_ssq[5][128];
__device__ uint32_t g_wimg[61440];          // packed half2 hi/lo weight images
__device__ float  g_zero[128];              // zero-initialized (never written)

#define OFF_C1L2 0
#define OFF_P2   4096
#define OFF_Q2   12288
#define OFF_C2L2 20480
#define OFF_CLS  36864

// ---------------- helpers -----------------------------------------------------
__device__ __forceinline__ uint32_t hpack(float v0, float v1, float& r0, float& r1) {
    __half h0 = __float2half_rn(v0), h1 = __float2half_rn(v1);
    r0 = v0 - __half2float(h0);
    r1 = v1 - __half2float(h1);
    __half2 p = __halves2half2(h0, h1);
    return *(uint32_t*)&p;
}
__device__ __forceinline__ uint32_t hpack2(float v0, float v1) {
    __half2 p = __halves2half2(__float2half_rn(v0), __float2half_rn(v1));
    return *(uint32_t*)&p;
}
__device__ __forceinline__ void mma16(float* c, const uint32_t* a, const uint32_t* b) {
    asm volatile("mma.sync.aligned.m16n8k16.row.col.f32.f16.f16.f32 "
        "{%0,%1,%2,%3}, {%4,%5,%6,%7}, {%8,%9}, {%0,%1,%2,%3};"
        : "+f"(c[0]), "+f"(c[1]), "+f"(c[2]), "+f"(c[3])
        : "r"(a[0]), "r"(a[1]), "r"(a[2]), "r"(a[3]), "r"(b[0]), "r"(b[1]));
}
__device__ __forceinline__ void affine_init(int stage, const float* gam, const float* bet,
                                            float n, int cout, float* sSc, float* sSh, int tid) {
    if (tid < cout) {
        double mean = g_sum[stage][tid] / (double)n;
        double var  = g_ssq[stage][tid] / (double)n - mean*mean;
        float  s    = gam[tid] / sqrtf((float)var + EPSI);
        sSc[tid] = s;
        sSh[tid] = bet[tid] - (float)mean * s;
    }
}

// ---------------- weight prep (single merged launch) --------------------------
__device__ __forceinline__ void wprep_plain_body(const float* W, uint32_t* dst,
                                                 int CIN, int COUT, int t) {
    if (t >= (CIN/2)*COUT) return;
    int k2 = t / COUT, n = t % COUT;
    float w0 = W[(size_t)(2*k2)*COUT + n], w1 = W[(size_t)(2*k2+1)*COUT + n];
    float r0, r1;
    dst[t] = hpack(w0, w1, r0, r1);
    dst[(CIN/2)*COUT + t] = hpack2(r0, r1);
}
__global__ void wprep_all(const float* __restrict__ c1w2, const float* __restrict__ c2w1,
                          const float* __restrict__ c2w2, const float* __restrict__ clsw1,
                          uint32_t* __restrict__ wimg) {
    int bid = blockIdx.x, tid = threadIdx.x;
    if (bid < 8) {
        wprep_plain_body(c1w2, wimg + OFF_C1L2, 64, 64, bid*256 + tid);
    } else if (bid < 24) {
        int t = (bid-8)*256 + tid;
        if (t < 32*128) {
            int k2 = t / 128, n = t % 128;
            float wt0 = c2w1[(size_t)(2*k2)*128 + n],    wt1 = c2w1[(size_t)(2*k2+1)*128 + n];
            float wb0 = c2w1[(size_t)(2*k2+64)*128 + n], wb1 = c2w1[(size_t)(2*k2+65)*128 + n];
            float r0, r1;
            wimg[OFF_P2 + t] = hpack(wt0 - wb0, wt1 - wb1, r0, r1);
            wimg[OFF_P2 + 32*128 + t] = hpack2(r0, r1);
            wimg[OFF_Q2 + t] = hpack(wb0, wb1, r0, r1);
            wimg[OFF_Q2 + 32*128 + t] = hpack2(r0, r1);
        }
    } else if (bid < 56) {
        wprep_plain_body(c2w2, wimg + OFF_C2L2, 128, 128, (bid-24)*256 + tid);
    } else {
        wprep_plain_body(clsw1, wimg + OFF_CLS, 192, 128, (bid-56)*256 + tid);
    }
}

// ---------------- knn for C=4 (+ stats zeroing) -------------------------------
__global__ void knn4_kernel(const float* __restrict__ Xin, int* __restrict__ out_idx) {
    constexpr int TI = 128, TJ = 128;
    __shared__ float4 sxj[TJ];
    __shared__ float  sx2[TJ];
    const float4* X4 = (const float4*)Xin;

    if (blockIdx.x == 0) {
        for (int t = threadIdx.x; t < 640; t += TI) {
            (&g_sum[0][0])[t] = 0.0; (&g_ssq[0][0])[t] = 0.0;
        }
    }
    int b = blockIdx.x / (NN / TI);
    int i = (blockIdx.x % (NN / TI)) * TI + threadIdx.x;

    float4 xi = X4[(size_t)b*NN + i];
    float x2i = xi.x*xi.x + xi.y*xi.y + xi.z*xi.z + xi.w*xi.w;

    float td[KKN]; int ti[KKN];
#pragma unroll
    for (int s = 0; s < KKN; s++) { td[s] = 3.4e38f; ti[s] = 0; }

    for (int j0 = 0; j0 < NN; j0 += TJ) {
        __syncthreads();
        {
            float4 v = X4[(size_t)b*NN + j0 + threadIdx.x];
            sxj[threadIdx.x] = v;
            sx2[threadIdx.x] = v.x*v.x + v.y*v.y + v.z*v.z + v.w*v.w;
        }
        __syncthreads();
        for (int jj = 0; jj < TJ; jj++) {
            float4 v = sxj[jj];
            float dot = xi.x*v.x + xi.y*v.y + xi.z*v.z + xi.w*v.w;
            float d = x2i + sx2[jj] - 2.0f*dot;
            if (d < td[KKN-1]) {
                td[KKN-1] = d; ti[KKN-1] = j0 + jj;
#pragma unroll
                for (int s = KKN-1; s > 0; s--) {
                    if (td[s] < td[s-1]) {
                        float t0 = td[s]; td[s] = td[s-1]; td[s-1] = t0;
                        int   u0 = ti[s]; ti[s] = ti[s-1]; ti[s-1] = u0;
                    }
                }
            }
        }
    }
#pragma unroll
    for (int s = 0; s < KKN; s++) out_idx[(size_t)(b*NN + i)*KKN + s] = ti[s];
}

// ---------------- P1/Q1 for edgeconv1 (CIN=4, SIMT) ---------------------------
__global__ void pq1_kernel(const float* __restrict__ X, const float* __restrict__ W,
                           const float* __restrict__ b1) {
    __shared__ float sWd[4*64], sWb[4*64], sB[64];
    int tid = threadIdx.x;
    {
        int ci = tid >> 6, c = tid & 63;
        sWd[ci*64+c] = W[ci*64+c] - W[(ci+4)*64+c];
        sWb[ci*64+c] = W[(ci+4)*64+c];
    }
    if (tid < 64) sB[tid] = b1[tid];
    __syncthreads();
    int c = tid & 63;
    int bn = blockIdx.x*4 + (tid >> 6);
    float4 x = ((const float4*)X)[bn];
    float p = sB[c] + x.x*sWd[c] + x.y*sWd[64+c] + x.z*sWd[128+c] + x.w*sWd[192+c];
    float q =         x.x*sWb[c] + x.y*sWb[64+c] + x.z*sWb[128+c] + x.w*sWb[192+c];
    g_P1[(size_t)bn*64 + c] = p;
    g_Q1[(size_t)bn*64 + c] = q;
}

// ---------------- layer-1 BN stats from P,Q over edges ------------------------
template<int COUT>
__global__ void stats1_kernel(const float* __restrict__ P, const float* __restrict__ Q,
                              int sstage, int r_base) {
    constexpr int G = 256 / COUT;
    constexpr int EPB = 320;
    __shared__ float sS[COUT], sQ2[COUT];
    int tid = threadIdx.x;
    int c = tid & (COUT-1), g = tid / COUT;
    if (tid < COUT) { sS[tid] = 0.f; sQ2[tid] = 0.f; }
    __syncthreads();
    int r0 = r_base + blockIdx.x * EPB;
    float s = 0.f, q = 0.f;
    for (int e = g; e < EPB; e += G) {
        int r = r0 + e;
        unsigned bn = (unsigned)r / KKN;
        int b = bn >> 12;
        int j = g_idx[r];
        float h = P[(size_t)bn*COUT + c] + Q[((size_t)(b<<12) + j)*COUT + c];
        s += h; q += h*h;
    }
    atomicAdd(&sS[c], s); atomicAdd(&sQ2[c], q);
    __syncthreads();
    if (tid < COUT) {
        atomicAdd(&g_sum[sstage][tid], (double)sS[tid]);
        atomicAdd(&g_ssq[sstage][tid], (double)sQ2[tid]);
    }
}

// ---------------- knn for C=64: fp16 4-term MMA Gram + insertion --------------
__global__ void __launch_bounds__(256, 1)
knn64_kernel(int* __restrict__ out_idx) {
    extern __shared__ uint32_t smu[];
    constexpr int AS = 36, BS = 136;
    uint32_t* XiH = smu;
    uint32_t* XiL = smu + 128*AS;
    uint32_t* XjH = smu + 2*128*AS;
    uint32_t* XjL = XjH + 32*BS;
    float* dist = (float*)(XjL + 32*BS);
    float* x2j  = dist + 128*133;

    int tid = threadIdx.x, wid = tid >> 5, lane = tid & 31;
    int gid = lane >> 2, tig = lane & 3;
    int b  = blockIdx.x >> 5;
    int i0 = (blockIdx.x & 31) * 128;
    int mbase = (wid >> 2) * 64;
    int nbase = (wid & 3) * 32;

    float x2i = 0.f;
    if (tid < 128) {
        const float4* row = (const float4*)&g_x1[(size_t)(b*NN + i0 + tid)*64];
#pragma unroll
        for (int q = 0; q < 16; q++) {
            float4 v = row[q];
            x2i += v.x*v.x + v.y*v.y + v.z*v.z + v.w*v.w;
            float r0, r1;
            XiH[tid*AS + 2*q]   = hpack(v.x, v.y, r0, r1);
            XiL[tid*AS + 2*q]   = hpack2(r0, r1);
            XiH[tid*AS + 2*q+1] = hpack(v.z, v.w, r0, r1);
            XiL[tid*AS + 2*q+1] = hpack2(r0, r1);
        }
    }
    float td[KKN]; int ti[KKN];
#pragma unroll
    for (int s = 0; s < KKN; s++) { td[s] = 3.4e38f; ti[s] = 0; }

    for (int jt = 0; jt < 32; jt++) {
        __syncthreads();
        if (tid < 128) {
            const float4* row = (const float4*)&g_x1[(size_t)(b*NN + jt*128 + tid)*64];
            float s2 = 0.f;
#pragma unroll
            for (int q = 0; q < 16; q++) {
                float4 v = row[q];
                s2 += v.x*v.x + v.y*v.y + v.z*v.z + v.w*v.w;
                float r0, r1;
                XjH[(2*q)*BS + tid]   = hpack(v.x, v.y, r0, r1);
                XjL[(2*q)*BS + tid]   = hpack2(r0, r1);
                XjH[(2*q+1)*BS + tid] = hpack(v.z, v.w, r0, r1);
                XjL[(2*q+1)*BS + tid] = hpack2(r0, r1);
            }
            x2j[tid] = s2;
        }
        __syncthreads();

        float acc[4][4][4];
#pragma unroll
        for (int mt = 0; mt < 4; mt++)
#pragma unroll
            for (int nt = 0; nt < 4; nt++)
#pragma unroll
                for (int u = 0; u < 4; u++) acc[mt][nt][u] = 0.f;

#pragma unroll
        for (int kk = 0; kk < 4; kk++) {
            int k2b = kk*8;
            uint32_t ah[4][4], al[4][4], bh[4][2], bl[4][2];
#pragma unroll
            for (int mt = 0; mt < 4; mt++) {
                int rb = mbase + mt*16 + gid;
                ah[mt][0] = XiH[rb*AS + k2b + tig];
                ah[mt][1] = XiH[(rb+8)*AS + k2b + tig];
                ah[mt][2] = XiH[rb*AS + k2b + tig + 4];
                ah[mt][3] = XiH[(rb+8)*AS + k2b + tig + 4];
                al[mt][0] = XiL[rb*AS + k2b + tig];
                al[mt][1] = XiL[(rb+8)*AS + k2b + tig];
                al[mt][2] = XiL[rb*AS + k2b + tig + 4];
                al[mt][3] = XiL[(rb+8)*AS + k2b + tig + 4];
            }
#pragma unroll
            for (int nt = 0; nt < 4; nt++) {
                int cb = nbase + nt*8 + gid;
                bh[nt][0] = XjH[(k2b + tig)*BS + cb];
                bh[nt][1] = XjH[(k2b + tig + 4)*BS + cb];
                bl[nt][0] = XjL[(k2b + tig)*BS + cb];
                bl[nt][1] = XjL[(k2b + tig + 4)*BS + cb];
            }
#pragma unroll
            for (int mt = 0; mt < 4; mt++)
#pragma unroll
                for (int nt = 0; nt < 4; nt++) {
                    mma16(acc[mt][nt], ah[mt], bh[nt]);
                    mma16(acc[mt][nt], ah[mt], bl[nt]);
                    mma16(acc[mt][nt], al[mt], bh[nt]);
                    mma16(acc[mt][nt], al[mt], bl[nt]);   // ll: fp32-exact distances
                }
        }
#pragma unroll
        for (int mt = 0; mt < 4; mt++)
#pragma unroll
            for (int nt = 0; nt < 4; nt++) {
                int row = mbase + mt*16 + gid;
                int col = nbase + nt*8 + tig*2;
                dist[row*133 + col]         = acc[mt][nt][0];
                dist[row*133 + col + 1]     = acc[mt][nt][1];
                dist[(row+8)*133 + col]     = acc[mt][nt][2];
                dist[(row+8)*133 + col + 1] = acc[mt][nt][3];
            }
        __syncthreads();
        if (tid < 128) {
            const float* drow = &dist[tid*133];
            for (int jj = 0; jj < 128; jj++) {
                float d = x2i + x2j[jj] - 2.0f*drow[jj];
                if (d < td[KKN-1]) {
                    td[KKN-1] = d; ti[KKN-1] = jt*128 + jj;
#pragma unroll
                    for (int s = KKN-1; s > 0; s--) {
                        if (td[s] < td[s-1]) {
                            float t0 = td[s]; td[s] = td[s-1]; td[s-1] = t0;
                            int   u0 = ti[s]; ti[s] = ti[s-1]; ti[s-1] = u0;
                        }
                    }
                }
            }
        }
    }
    if (tid < 128) {
#pragma unroll
        for (int s = 0; s < KKN; s++)
            out_idx[(size_t)(b*NN + i0 + tid)*KKN + s] = ti[s];
    }
}

// ================= fp16-split warp-MMA GEMM + fused epilogue =================
// MODE 2: cls, A = concat(g_x1, g_x2), stats->sstage, out g_h
// MODE 3: edge layer2, A = relu(bn(P_i + Q_j)), stats->sstage, out g_h
// MODE 4: PQ gemm, A = Pin rows, no stats, out Hout (+bias or zeros)
template<int CIN, int COUT, int MODE>
__global__ void __launch_bounds__(256, 2)
tgemm_kernel(int sstage, int pstage, const uint32_t* __restrict__ Wimg,
             const float* __restrict__ bias,
             const float* __restrict__ gam, const float* __restrict__ bet, float nstat,
             const float* __restrict__ Pin, const float* __restrict__ Qin,
             float* __restrict__ Hout) {
    extern __shared__ uint32_t smu[];
    constexpr int NCH = CIN / 64;
    constexpr int AS  = 36;
    constexpr int BS  = COUT + 8;
    constexpr int MT  = (COUT == 128) ? 4 : 2;
    uint32_t* Ah = smu;
    uint32_t* Al = smu + 128*AS;
    uint32_t* Bh = smu + 2*128*AS;
    uint32_t* Bl = Bh + 32*BS;
    float* stg = (float*)smu;
    __shared__ float sSc[128], sSh[128];

    int tid = threadIdx.x, wid = tid >> 5, lane = tid & 31;
    int gid = lane >> 2, tig = lane & 3;
    int r0 = blockIdx.x * 128;

    if constexpr (MODE == 3) {
        affine_init(pstage, gam, bet, nstat, CIN, sSc, sSh, tid);
        __syncthreads();
    }

    int mbase = (COUT == 128) ? (wid >> 2) * 64 : (wid >> 1) * 32;
    int nbase = (COUT == 128) ? (wid & 3) * 32  : (wid & 1) * 32;

    float acc[MT][4][4];
#pragma unroll
    for (int mt = 0; mt < MT; mt++)
#pragma unroll
        for (int nt = 0; nt < 4; nt++)
#pragma unroll
            for (int u = 0; u < 4; u++) acc[mt][nt][u] = 0.f;

    for (int c = 0; c < NCH; c++) {
        if (c) __syncthreads();
        // ---- A chunk ----
        for (int e2 = tid; e2 < 128*32; e2 += 256) {
            int m = e2 >> 5, k2 = e2 & 31;
            int kc = c*64 + k2*2;
            int r = r0 + m;
            float v0, v1;
            if constexpr (MODE == 3) {
                unsigned bn = (unsigned)r / KKN;
                int b = bn >> 12;
                int j = g_idx[r];
                float2 p = *(const float2*)&Pin[(size_t)bn*CIN + kc];
                float2 q = *(const float2*)&Qin[((size_t)(b<<12) + j)*CIN + kc];
                v0 = fmaxf(fmaf(p.x + q.x, sSc[kc],   sSh[kc]),   0.f);
                v1 = fmaxf(fmaf(p.y + q.y, sSc[kc+1], sSh[kc+1]), 0.f);
            } else if constexpr (MODE == 4) {
                float2 p = *(const float2*)&Pin[(size_t)r*CIN + kc];
                v0 = p.x; v1 = p.y;
            } else {
                if (kc < 64) {
                    float2 p = *(const float2*)&g_x1[(size_t)r*64 + kc];
                    v0 = p.x; v1 = p.y;
                } else {
                    float2 p = *(const float2*)&g_x2[(size_t)r*128 + (kc - 64)];
                    v0 = p.x; v1 = p.y;
                }
            }
            float r0f, r1f;
            Ah[m*AS + k2] = hpack(v0, v1, r0f, r1f);
            Al[m*AS + k2] = hpack2(r0f, r1f);
        }
        // ---- B chunk: straight copy from packed image ----
        for (int e2 = tid; e2 < 32*COUT; e2 += 256) {
            int k2 = e2 / COUT, n = e2 % COUT;
            Bh[k2*BS + n] = Wimg[(size_t)(c*32 + k2)*COUT + n];
            Bl[k2*BS + n] = Wimg[(size_t)(CIN/2)*COUT + (size_t)(c*32 + k2)*COUT + n];
        }
        __syncthreads();
        // ---- compute ----
#pragma unroll
        for (int kk = 0; kk < 4; kk++) {
            int k2b = kk*8;
            uint32_t ah[MT][4], al[MT][4], bh[4][2], bl[4][2];
#pragma unroll
            for (int mt = 0; mt < MT; mt++) {
                int rb = mbase + mt*16 + gid;
                ah[mt][0] = Ah[rb*AS + k2b + tig];
                ah[mt][1] = Ah[(rb+8)*AS + k2b + tig];
                ah[mt][2] = Ah[rb*AS + k2b + tig + 4];
                ah[mt][3] = Ah[(rb+8)*AS + k2b + tig + 4];
                al[mt][0] = Al[rb*AS + k2b + tig];
                al[mt][1] = Al[(rb+8)*AS + k2b + tig];
                al[mt][2] = Al[rb*AS + k2b + tig + 4];
                al[mt][3] = Al[(rb+8)*AS + k2b + tig + 4];
            }
#pragma unroll
            for (int nt = 0; nt < 4; nt++) {
                int cb = nbase + nt*8 + gid;
                bh[nt][0] = Bh[(k2b + tig)*BS + cb];
                bh[nt][1] = Bh[(k2b + tig + 4)*BS + cb];
                bl[nt][0] = Bl[(k2b + tig)*BS + cb];
                bl[nt][1] = Bl[(k2b + tig + 4)*BS + cb];
            }
#pragma unroll
            for (int mt = 0; mt < MT; mt++)
#pragma unroll
                for (int nt = 0; nt < 4; nt++) {
                    mma16(acc[mt][nt], ah[mt], bh[nt]);
                    mma16(acc[mt][nt], ah[mt], bl[nt]);
                    mma16(acc[mt][nt], al[mt], bh[nt]);
                }
        }
    }
    __syncthreads();
    // ---- epilogue: frags + bias -> stage ----
#pragma unroll
    for (int mt = 0; mt < MT; mt++)
#pragma unroll
        for (int nt = 0; nt < 4; nt++) {
            int row = mbase + mt*16 + gid;
            int col = nbase + nt*8 + tig*2;
            float b0 = bias[col], b1 = bias[col+1];
            stg[row*(COUT+1) + col]         = acc[mt][nt][0] + b0;
            stg[row*(COUT+1) + col + 1]     = acc[mt][nt][1] + b1;
            stg[(row+8)*(COUT+1) + col]     = acc[mt][nt][2] + b0;
            stg[(row+8)*(COUT+1) + col + 1] = acc[mt][nt][3] + b1;
        }
    __syncthreads();
    if constexpr (MODE != 4) {
        if (tid < COUT) {
            float s = 0.f, q = 0.f;
#pragma unroll 8
            for (int r = 0; r < 128; r++) {
                float v = stg[r*(COUT+1) + tid];
                s += v; q += v*v;
            }
            atomicAdd(&g_sum[sstage][tid], (double)s);
            atomicAdd(&g_ssq[sstage][tid], (double)q);
        }
    }
    float* dst = (MODE == 4) ? Hout : g_h;
    for (int e = tid; e < 128*(COUT/4); e += 256) {
        int r = e / (COUT/4), c4 = e % (COUT/4);
        const float* p = &stg[r*(COUT+1) + c4*4];
        float4 v = make_float4(p[0], p[1], p[2], p[3]);
        *(float4*)&dst[(size_t)(r0 + r)*COUT + c4*4] = v;
    }
}

// ---------------- BN+relu + max over k --------------------------------------
template<int COUT>
__global__ void maxpool_kernel(int pstage, const float* __restrict__ gam,
                               const float* __restrict__ bet, float nstat) {
    __shared__ float sSc[COUT], sSh[COUT];
    affine_init(pstage, gam, bet, nstat, COUT, sSc, sSh, threadIdx.x);
    __syncthreads();
    int t = blockIdx.x * 256 + threadIdx.x;
    int c  = t & (COUT - 1);
    int bn = t >> (COUT == 64 ? 6 : 7);
    float s  = sSc[c], sh = sSh[c];
    const float* base = &g_h[((size_t)bn * KKN) * COUT + c];
    float m = -3.4e38f;
#pragma unroll
    for (int kk = 0; kk < KKN; kk++)
        m = fmaxf(m, fmaf(base[(size_t)kk*COUT], s, sh));
    m = fmaxf(m, 0.f);
    if (COUT == 64) g_x1[t] = m; else g_x2[t] = m;
}

// ---------------- classifier final -------------------------------------------
__global__ void cls_final_kernel(const float* __restrict__ W2,
                                 const float* __restrict__ B2,
                                 const float* __restrict__ gam,
                                 const float* __restrict__ bet,
                                 float* __restrict__ out) {
    __shared__ float sSc[128], sSh[128];
    affine_init(4, gam, bet, (float)BN_TOTAL, 128, sSc, sSh, threadIdx.x);
    __syncthreads();
    int gw   = (blockIdx.x * blockDim.x + threadIdx.x) >> 5;
    int lane = threadIdx.x & 31;
    const float* hrow = &g_h[(size_t)gw * 128];
    float p = 0.f;
#pragma unroll
    for (int q = 0; q < 4; q++) {
        int c = lane + 32*q;
        float v = fmaxf(fmaf(hrow[c], sSc[c], sSh[c]), 0.f);
        p = fmaf(v, W2[c], p);
    }
#pragma unroll
    for (int o = 16; o > 0; o >>= 1) p += __shfl_down_sync(0xffffffffu, p, o);
    if (lane == 0) out[gw] = p + B2[0];
}

// ---------------- host orchestration ----------------------------------------
extern "C" void kernel_launch(void* const* d_in, const int* in_sizes, int n_in,
                              void* d_out, int out_size) {
    const float* x      = (const float*)d_in[0];
    const float* c1_w1  = (const float*)d_in[1];
    const float* c1_b1  = (const float*)d_in[2];
    const float* c1_g1  = (const float*)d_in[3];
    const float* c1_be1 = (const float*)d_in[4];
    const float* c1_w2  = (const float*)d_in[5];
    const float* c1_b2  = (const float*)d_in[6];
    const float* c1_g2  = (const float*)d_in[7];
    const float* c1_be2 = (const float*)d_in[8];
    const float* c2_w1  = (const float*)d_in[9];
    const float* c2_b1  = (const float*)d_in[10];
    const float* c2_g1  = (const float*)d_in[11];
    const float* c2_be1 = (const float*)d_in[12];
    const float* c2_w2  = (const float*)d_in[13];
    const float* c2_b2  = (const float*)d_in[14];
    const float* c2_g2  = (const float*)d_in[15];
    const float* c2_be2 = (const float*)d_in[16];
    const float* cls_w1 = (const float*)d_in[17];
    const float* cls_b1 = (const float*)d_in[18];
    const float* cls_g1 = (const float*)d_in[19];
    const float* cls_be1= (const float*)d_in[20];
    const float* cls_w2 = (const float*)d_in[21];
    const float* cls_b2 = (const float*)d_in[22];
    float* out = (float*)d_out;

    int* idx_ptr;   cudaGetSymbolAddress((void**)&idx_ptr, g_idx);
    uint32_t* wimg; cudaGetSymbolAddress((void**)&wimg, g_wimg);
    float *p1, *q1, *p2, *q2, *zero, *x1;
    cudaGetSymbolAddress((void**)&p1, g_P1);
    cudaGetSymbolAddress((void**)&q1, g_Q1);
    cudaGetSymbolAddress((void**)&p2, g_P2);
    cudaGetSymbolAddress((void**)&q2, g_Q2);
    cudaGetSymbolAddress((void**)&zero, g_zero);
    cudaGetSymbolAddress((void**)&x1, g_x1);     // FIX: device address, not host shadow

    const int SMB128 = (2*128*36 + 2*32*136) * 4;
    const int SMB64  = (2*128*36 + 2*32*72)  * 4;
    const int SMKNN  = (2*128*36 + 2*32*136 + 128*133 + 128) * 4;
    cudaFuncSetAttribute(tgemm_kernel<64,64,3>,   cudaFuncAttributeMaxDynamicSharedMemorySize, SMB64);
    cudaFuncSetAttribute(tgemm_kernel<64,128,4>,  cudaFuncAttributeMaxDynamicSharedMemorySize, SMB128);
    cudaFuncSetAttribute(tgemm_kernel<128,128,3>, cudaFuncAttributeMaxDynamicSharedMemorySize, SMB128);
    cudaFuncSetAttribute(tgemm_kernel<192,128,2>, cudaFuncAttributeMaxDynamicSharedMemorySize, SMB128);
    cudaFuncSetAttribute(knn64_kernel,            cudaFuncAttributeMaxDynamicSharedMemorySize, SMKNN);

    // ---- EdgeConv 1 ----  (launch order: #6 = tgemm<64,64,3> for ncu -s 5 -c 1)
    wprep_all<<<104, 256>>>(c1_w2, c2_w1, c2_w2, cls_w1, wimg);                       // 1
    knn4_kernel<<<BB*(NN/128), 128>>>(x, idx_ptr);                                    // 2
    pq1_kernel<<<BN_TOTAL/4, 256>>>(x, c1_w1, c1_b1);                                 // 3
    stats1_kernel<64><<<R_EDGE/640, 256>>>(p1, q1, 0, 0);                             // 4
    stats1_kernel<64><<<R_EDGE/640, 256>>>(p1, q1, 0, R_EDGE/2);                      // 5
    tgemm_kernel<64,64,3><<<R_EDGE/128, 256, SMB64>>>(1, 0, wimg + OFF_C1L2, c1_b2,
        c1_g1, c1_be1, (float)R_EDGE, p1, q1, nullptr);                               // 6 <- ncu
    maxpool_kernel<64><<<BN_TOTAL*64/256, 256>>>(1, c1_g2, c1_be2, (float)R_EDGE);

    // ---- EdgeConv 2 ----
    knn64_kernel<<<BB*32, 256, SMKNN>>>(idx_ptr);
    tgemm_kernel<64,128,4><<<BN_TOTAL/128, 256, SMB128>>>(-1, 0, wimg + OFF_P2, c2_b1,
        nullptr, nullptr, 0.f, x1, nullptr, p2);
    tgemm_kernel<64,128,4><<<BN_TOTAL/128, 256, SMB128>>>(-1, 0, wimg + OFF_Q2, zero,
        nullptr, nullptr, 0.f, x1, nullptr, q2);
    stats1_kernel<128><<<R_EDGE/320, 256>>>(p2, q2, 2, 0);
    tgemm_kernel<128,128,3><<<R_EDGE/128, 256, SMB128>>>(3, 2, wimg + OFF_C2L2, c2_b2,
        c2_g1, c2_be1, (float)R_EDGE, p2, q2, nullptr);
    maxpool_kernel<128><<<BN_TOTAL*128/256, 256>>>(3, c2_g2, c2_be2, (float)R_EDGE);

    // ---- Classifier ----
    tgemm_kernel<192,128,2><<<BN_TOTAL/128, 256, SMB128>>>(4, 0, wimg + OFF_CLS, cls_b1,
        nullptr, nullptr, 0.f, nullptr, nullptr, nullptr);
    cls_final_kernel<<<BN_TOTAL/8, 256>>>(cls_w2, cls_b2, cls_g1, cls_be1, out);
}

// round 7
// speedup vs baseline: 1.5380x; 1.0334x over previous
#include <cuda_runtime.h>
#include <cuda_fp16.h>
#include <math.h>
#include <stdint.h>

#define BB 8
#define NN 4096
#define KKN 20
#define BN_TOTAL (BB*NN)          // 32768
#define R_EDGE (BB*NN*KKN)        // 655360
#define EPSI 1e-5f

// ---------------- scratch (device globals; no allocation allowed) ------------
__device__ float    g_h[(size_t)BN_TOTAL*128];   // classifier hidden only (16 MB)
__device__ float    g_x1[BN_TOTAL*64];           // finalized edgeconv1 output
__device__ float    g_P1[BN_TOTAL*64],  g_Q1[BN_TOTAL*64];
__device__ float    g_P2[BN_TOTAL*128], g_Q2[BN_TOTAL*128];
__device__ uint32_t g_x1mx[BN_TOTAL*64],  g_x1mn[BN_TOTAL*64];
__device__ uint32_t g_x2mx[BN_TOTAL*128], g_x2mn[BN_TOTAL*128];
__device__ int      g_idx[R_EDGE];
__device__ double   g_sum[5][128];
__device__ double   g_ssq[5][128];
__device__ uint32_t g_wimg[61440];
__device__ float    g_zero[128];                 // zero-initialized (never written)

#define OFF_C1L2 0
#define OFF_P2   4096
#define OFF_Q2   12288
#define OFF_C2L2 20480
#define OFF_CLS  36864

// ---------------- helpers -----------------------------------------------------
__device__ __forceinline__ uint32_t hpack(float v0, float v1, float& r0, float& r1) {
    __half h0 = __float2half_rn(v0), h1 = __float2half_rn(v1);
    r0 = v0 - __half2float(h0);
    r1 = v1 - __half2float(h1);
    __half2 p = __halves2half2(h0, h1);
    return *(uint32_t*)&p;
}
__device__ __forceinline__ uint32_t hpack2(float v0, float v1) {
    __half2 p = __halves2half2(__float2half_rn(v0), __float2half_rn(v1));
    return *(uint32_t*)&p;
}
__device__ __forceinline__ void mma16(float* c, const uint32_t* a, const uint32_t* b) {
    asm volatile("mma.sync.aligned.m16n8k16.row.col.f32.f16.f16.f32 "
        "{%0,%1,%2,%3}, {%4,%5,%6,%7}, {%8,%9}, {%0,%1,%2,%3};"
        : "+f"(c[0]), "+f"(c[1]), "+f"(c[2]), "+f"(c[3])
        : "r"(a[0]), "r"(a[1]), "r"(a[2]), "r"(a[3]), "r"(b[0]), "r"(b[1]));
}
__device__ __forceinline__ void affine_init(int stage, const float* gam, const float* bet,
                                            float n, int cout, float* sSc, float* sSh, int tid) {
    if (tid < cout) {
        double mean = g_sum[stage][tid] / (double)n;
        double var  = g_ssq[stage][tid] / (double)n - mean*mean;
        float  s    = gam[tid] / sqrtf((float)var + EPSI);
        sSc[tid] = s;
        sSh[tid] = bet[tid] - (float)mean * s;
    }
}
// order-preserving float<->uint keys for atomic max/min
__device__ __forceinline__ uint32_t fkey(float f) {
    uint32_t u = __float_as_uint(f);
    return u ^ ((u >> 31) ? 0xffffffffu : 0x80000000u);
}
__device__ __forceinline__ float funkey(uint32_t u) {
    return __uint_as_float(u ^ ((u >> 31) ? 0x80000000u : 0xffffffffu));
}

// ---------------- knn for C=4 (+ stats zeroing) -------------------------------
__global__ void knn4_kernel(const float* __restrict__ Xin, int* __restrict__ out_idx) {
    constexpr int TI = 128, TJ = 128;
    __shared__ float4 sxj[TJ];
    __shared__ float  sx2[TJ];
    const float4* X4 = (const float4*)Xin;

    if (blockIdx.x == 0) {
        for (int t = threadIdx.x; t < 640; t += TI) {
            (&g_sum[0][0])[t] = 0.0; (&g_ssq[0][0])[t] = 0.0;
        }
    }
    int b = blockIdx.x / (NN / TI);
    int i = (blockIdx.x % (NN / TI)) * TI + threadIdx.x;

    float4 xi = X4[(size_t)b*NN + i];
    float x2i = xi.x*xi.x + xi.y*xi.y + xi.z*xi.z + xi.w*xi.w;

    float td[KKN]; int ti[KKN];
#pragma unroll
    for (int s = 0; s < KKN; s++) { td[s] = 3.4e38f; ti[s] = 0; }

    for (int j0 = 0; j0 < NN; j0 += TJ) {
        __syncthreads();
        {
            float4 v = X4[(size_t)b*NN + j0 + threadIdx.x];
            sxj[threadIdx.x] = v;
            sx2[threadIdx.x] = v.x*v.x + v.y*v.y + v.z*v.z + v.w*v.w;
        }
        __syncthreads();
        for (int jj = 0; jj < TJ; jj++) {
            float4 v = sxj[jj];
            float dot = xi.x*v.x + xi.y*v.y + xi.z*v.z + xi.w*v.w;
            float d = x2i + sx2[jj] - 2.0f*dot;
            if (d < td[KKN-1]) {
                td[KKN-1] = d; ti[KKN-1] = j0 + jj;
#pragma unroll
                for (int s = KKN-1; s > 0; s--) {
                    if (td[s] < td[s-1]) {
                        float t0 = td[s]; td[s] = td[s-1]; td[s-1] = t0;
                        int   u0 = ti[s]; ti[s] = ti[s-1]; ti[s-1] = u0;
                    }
                }
            }
        }
    }
#pragma unroll
    for (int s = 0; s < KKN; s++) out_idx[(size_t)(b*NN + i)*KKN + s] = ti[s];
}

// ---------------- prep: pq1 + weight prep + max/min buffer init ---------------
__global__ void prep_kernel(const float* __restrict__ X, const float* __restrict__ c1w1,
                            const float* __restrict__ c1b1, const float* __restrict__ c1w2,
                            const float* __restrict__ c2w1, const float* __restrict__ c2w2,
                            const float* __restrict__ clsw1, uint32_t* __restrict__ wimg) {
    __shared__ float sWd[4*64], sWb[4*64], sB[64];
    int bid = blockIdx.x, tid = threadIdx.x;
    if (bid < 8192) {
        // P1/Q1 (factorized edgeconv1 layer1)
        {
            int ci = tid >> 6, c = tid & 63;
            sWd[ci*64+c] = c1w1[ci*64+c] - c1w1[(ci+4)*64+c];
            sWb[ci*64+c] = c1w1[(ci+4)*64+c];
        }
        if (tid < 64) sB[tid] = c1b1[tid];
        __syncthreads();
        int c = tid & 63;
        int bn = bid*4 + (tid >> 6);
        float4 x = ((const float4*)X)[bn];
        float p = sB[c] + x.x*sWd[c] + x.y*sWd[64+c] + x.z*sWd[128+c] + x.w*sWd[192+c];
        float q =         x.x*sWb[c] + x.y*sWb[64+c] + x.z*sWb[128+c] + x.w*sWb[192+c];
        g_P1[(size_t)bn*64 + c] = p;
        g_Q1[(size_t)bn*64 + c] = q;
    } else if (bid < 8296) {
        int wb = bid - 8192;
        if (wb < 8) {
            int t = wb*256 + tid;
            if (t < 32*64) {
                int k2 = t / 64, n = t % 64;
                float w0 = c1w2[(size_t)(2*k2)*64 + n], w1 = c1w2[(size_t)(2*k2+1)*64 + n];
                float r0, r1;
                wimg[OFF_C1L2 + t] = hpack(w0, w1, r0, r1);
                wimg[OFF_C1L2 + 32*64 + t] = hpack2(r0, r1);
            }
        } else if (wb < 24) {
            int t = (wb-8)*256 + tid;
            if (t < 32*128) {
                int k2 = t / 128, n = t % 128;
                float wt0 = c2w1[(size_t)(2*k2)*128 + n],    wt1 = c2w1[(size_t)(2*k2+1)*128 + n];
                float wb0 = c2w1[(size_t)(2*k2+64)*128 + n], wb1 = c2w1[(size_t)(2*k2+65)*128 + n];
                float r0, r1;
                wimg[OFF_P2 + t] = hpack(wt0 - wb0, wt1 - wb1, r0, r1);
                wimg[OFF_P2 + 32*128 + t] = hpack2(r0, r1);
                wimg[OFF_Q2 + t] = hpack(wb0, wb1, r0, r1);
                wimg[OFF_Q2 + 32*128 + t] = hpack2(r0, r1);
            }
        } else if (wb < 56) {
            int t = (wb-24)*256 + tid;
            if (t < 64*128) {
                int k2 = t / 128, n = t % 128;
                float w0 = c2w2[(size_t)(2*k2)*128 + n], w1 = c2w2[(size_t)(2*k2+1)*128 + n];
                float r0, r1;
                wimg[OFF_C2L2 + t] = hpack(w0, w1, r0, r1);
                wimg[OFF_C2L2 + 64*128 + t] = hpack2(r0, r1);
            }
        } else {
            int t = (wb-56)*256 + tid;
            if (t < 96*128) {
                int k2 = t / 128, n = t % 128;
                float w0 = clsw1[(size_t)(2*k2)*128 + n], w1 = clsw1[(size_t)(2*k2+1)*128 + n];
                float r0, r1;
                wimg[OFF_CLS + t] = hpack(w0, w1, r0, r1);
                wimg[OFF_CLS + 96*128 + t] = hpack2(r0, r1);
            }
        }
    } else {
        // init max/min buffers: 6144 blocks x 2048 u32
        int rel = bid - 8296;
        uint32_t* dst; uint32_t val;
        size_t off;
        if (rel < 1024)      { dst = g_x1mx; val = 0u;          off = (size_t)rel*2048; }
        else if (rel < 2048) { dst = g_x1mn; val = 0xffffffffu; off = (size_t)(rel-1024)*2048; }
        else if (rel < 4096) { dst = g_x2mx; val = 0u;          off = (size_t)(rel-2048)*2048; }
        else                 { dst = g_x2mn; val = 0xffffffffu; off = (size_t)(rel-4096)*2048; }
        uint4 v4 = make_uint4(val, val, val, val);
        uint4* d4 = (uint4*)(dst + off);
#pragma unroll
        for (int u = 0; u < 2; u++) d4[tid + 256*u] = v4;
    }
}

// ---------------- layer-1 BN stats from P,Q over edges ------------------------
template<int COUT>
__global__ void stats1_kernel(const float* __restrict__ P, const float* __restrict__ Q,
                              int sstage) {
    constexpr int G = 256 / COUT;
    constexpr int EPB = 320;
    __shared__ float sS[COUT], sQ2[COUT];
    int tid = threadIdx.x;
    int c = tid & (COUT-1), g = tid / COUT;
    if (tid < COUT) { sS[tid] = 0.f; sQ2[tid] = 0.f; }
    __syncthreads();
    int r0 = blockIdx.x * EPB;
    float s = 0.f, q = 0.f;
    for (int e = g; e < EPB; e += G) {
        int r = r0 + e;
        unsigned bn = (unsigned)r / KKN;
        int b = bn >> 12;
        int j = g_idx[r];
        float h = P[(size_t)bn*COUT + c] + Q[((size_t)(b<<12) + j)*COUT + c];
        s += h; q += h*h;
    }
    atomicAdd(&sS[c], s); atomicAdd(&sQ2[c], q);
    __syncthreads();
    if (tid < COUT) {
        atomicAdd(&g_sum[sstage][tid], (double)sS[tid]);
        atomicAdd(&g_ssq[sstage][tid], (double)sQ2[tid]);
    }
}

// ---------------- finalize x1: relu(bn(max/min)) ------------------------------
__global__ void finalize_x1_kernel(const float* __restrict__ gam,
                                   const float* __restrict__ bet) {
    __shared__ float sSc[64], sSh[64];
    affine_init(1, gam, bet, (float)R_EDGE, 64, sSc, sSh, threadIdx.x);
    __syncthreads();
    int t = blockIdx.x*256 + threadIdx.x;
    int c = t & 63;
    float s = sSc[c];
    uint32_t u = (s >= 0.f) ? g_x1mx[t] : g_x1mn[t];
    g_x1[t] = fmaxf(fmaf(funkey(u), s, sSh[c]), 0.f);
}

// ---------------- knn for C=64: fp16 4-term MMA Gram, 256-thread select -------
__global__ void __launch_bounds__(256, 1)
knn64_kernel(int* __restrict__ out_idx) {
    extern __shared__ uint32_t smu[];
    constexpr int AS = 36, BS = 136;
    uint32_t* XiH = smu;
    uint32_t* XiL = smu + 128*AS;
    uint32_t* XjH = smu + 2*128*AS;
    uint32_t* XjL = XjH + 32*BS;
    float* dist = (float*)(XjL + 32*BS);
    float* x2ip = dist + 128*133;        // [2][128]
    float* x2jp = x2ip + 256;            // [2][128]

    int tid = threadIdx.x, wid = tid >> 5, lane = tid & 31;
    int gid = lane >> 2, tig = lane & 3;
    int b  = blockIdx.x >> 5;
    int i0 = (blockIdx.x & 31) * 128;
    int mbase = (wid >> 2) * 64;
    int nbase = (wid & 3) * 32;
    int rrow = tid & 127, hf = tid >> 7;     // load/select row + half

    // load Xi (split across 256 threads)
    {
        const float4* row = (const float4*)&g_x1[(size_t)(b*NN + i0 + rrow)*64];
        float part = 0.f;
#pragma unroll
        for (int qq = 0; qq < 8; qq++) {
            int q = hf*8 + qq;
            float4 v = row[q];
            part += v.x*v.x + v.y*v.y + v.z*v.z + v.w*v.w;
            float r0, r1;
            XiH[rrow*AS + 2*q]   = hpack(v.x, v.y, r0, r1);
            XiL[rrow*AS + 2*q]   = hpack2(r0, r1);
            XiH[rrow*AS + 2*q+1] = hpack(v.z, v.w, r0, r1);
            XiL[rrow*AS + 2*q+1] = hpack2(r0, r1);
        }
        x2ip[hf*128 + rrow] = part;
    }

    float td[KKN]; int ti[KKN];
#pragma unroll
    for (int s = 0; s < KKN; s++) { td[s] = 3.4e38f; ti[s] = 0; }

    for (int jt = 0; jt < 32; jt++) {
        __syncthreads();
        {
            const float4* row = (const float4*)&g_x1[(size_t)(b*NN + jt*128 + rrow)*64];
            float part = 0.f;
#pragma unroll
            for (int qq = 0; qq < 8; qq++) {
                int q = hf*8 + qq;
                float4 v = row[q];
                part += v.x*v.x + v.y*v.y + v.z*v.z + v.w*v.w;
                float r0, r1;
                XjH[(2*q)*BS + rrow]   = hpack(v.x, v.y, r0, r1);
                XjL[(2*q)*BS + rrow]   = hpack2(r0, r1);
                XjH[(2*q+1)*BS + rrow] = hpack(v.z, v.w, r0, r1);
                XjL[(2*q+1)*BS + rrow] = hpack2(r0, r1);
            }
            x2jp[hf*128 + rrow] = part;
        }
        __syncthreads();

        float acc[4][4][4];
#pragma unroll
        for (int mt = 0; mt < 4; mt++)
#pragma unroll
            for (int nt = 0; nt < 4; nt++)
#pragma unroll
                for (int u = 0; u < 4; u++) acc[mt][nt][u] = 0.f;

#pragma unroll
        for (int kk = 0; kk < 4; kk++) {
            int k2b = kk*8;
            uint32_t ah[4][4], al[4][4], bh[4][2], bl[4][2];
#pragma unroll
            for (int mt = 0; mt < 4; mt++) {
                int rb = mbase + mt*16 + gid;
                ah[mt][0] = XiH[rb*AS + k2b + tig];
                ah[mt][1] = XiH[(rb+8)*AS + k2b + tig];
                ah[mt][2] = XiH[rb*AS + k2b + tig + 4];
                ah[mt][3] = XiH[(rb+8)*AS + k2b + tig + 4];
                al[mt][0] = XiL[rb*AS + k2b + tig];
                al[mt][1] = XiL[(rb+8)*AS + k2b + tig];
                al[mt][2] = XiL[rb*AS + k2b + tig + 4];
                al[mt][3] = XiL[(rb+8)*AS + k2b + tig + 4];
            }
#pragma unroll
            for (int nt = 0; nt < 4; nt++) {
                int cb = nbase + nt*8 + gid;
                bh[nt][0] = XjH[(k2b + tig)*BS + cb];
                bh[nt][1] = XjH[(k2b + tig + 4)*BS + cb];
                bl[nt][0] = XjL[(k2b + tig)*BS + cb];
                bl[nt][1] = XjL[(k2b + tig + 4)*BS + cb];
            }
#pragma unroll
            for (int mt = 0; mt < 4; mt++)
#pragma unroll
                for (int nt = 0; nt < 4; nt++) {
                    mma16(acc[mt][nt], ah[mt], bh[nt]);
                    mma16(acc[mt][nt], ah[mt], bl[nt]);
                    mma16(acc[mt][nt], al[mt], bh[nt]);
                    mma16(acc[mt][nt], al[mt], bl[nt]);
                }
        }
#pragma unroll
        for (int mt = 0; mt < 4; mt++)
#pragma unroll
            for (int nt = 0; nt < 4; nt++) {
                int row = mbase + mt*16 + gid;
                int col = nbase + nt*8 + tig*2;
                dist[row*133 + col]         = acc[mt][nt][0];
                dist[row*133 + col + 1]     = acc[mt][nt][1];
                dist[(row+8)*133 + col]     = acc[mt][nt][2];
                dist[(row+8)*133 + col + 1] = acc[mt][nt][3];
            }
        __syncthreads();
        // 256-thread selection: half-block scans cols [hf*64, hf*64+64)
        {
            float x2i = x2ip[rrow] + x2ip[128 + rrow];
            const float* drow = &dist[rrow*133 + hf*64];
            const float* xa = x2jp + hf*64;
            const float* xb = x2jp + 128 + hf*64;
            for (int jj = 0; jj < 64; jj++) {
                float d = x2i + xa[jj] + xb[jj] - 2.0f*drow[jj];
                if (d < td[KKN-1]) {
                    td[KKN-1] = d; ti[KKN-1] = jt*128 + hf*64 + jj;
#pragma unroll
                    for (int s = KKN-1; s > 0; s--) {
                        if (td[s] < td[s-1]) {
                            float t0 = td[s]; td[s] = td[s-1]; td[s-1] = t0;
                            int   u0 = ti[s]; ti[s] = ti[s-1]; ti[s-1] = u0;
                        }
                    }
                }
            }
        }
    }
    // merge the two half-lists per row
    __syncthreads();
    float* md = dist;                      // [128][20]
    int*   mi = (int*)(dist + 2560);       // [128][20]
    if (hf == 1) {
#pragma unroll
        for (int s = 0; s < KKN; s++) { md[rrow*20 + s] = td[s]; mi[rrow*20 + s] = ti[s]; }
    }
    __syncthreads();
    if (hf == 0) {
        int a = 0, bb2 = 0;
        int* orow = &out_idx[(size_t)(b*NN + i0 + rrow)*KKN];
#pragma unroll
        for (int s = 0; s < KKN; s++) {
            float da = td[a], db = md[rrow*20 + bb2];
            int ja = ti[a],  jb = mi[rrow*20 + bb2];
            bool takeA = (da < db) || (da == db && ja < jb);
            orow[s] = takeA ? ja : jb;
            if (takeA) a++; else bb2++;
        }
    }
}

// ================= fp16-split warp-MMA GEMM + fused epilogue =================
// MODE 2: cls, A = concat(x1, decode(bn(x2raw))), stats->sstage, out g_h
// MODE 3: edge layer2, A = relu(bn(P_i + Q_j)), stats->sstage, out per-point max/min
// MODE 4: plain, A = Pin rows, no stats, out Hout
template<int CIN, int COUT, int MODE>
__global__ void __launch_bounds__(256, 2)
tgemm_kernel(int sstage, int pstage, const uint32_t* __restrict__ Wimg,
             const float* __restrict__ bias,
             const float* __restrict__ gam, const float* __restrict__ bet, float nstat,
             const float* __restrict__ Pin, const float* __restrict__ Qin,
             float* __restrict__ Hout,
             uint32_t* __restrict__ dmx, uint32_t* __restrict__ dmn) {
    extern __shared__ uint32_t smu[];
    constexpr int NCH = CIN / 64;
    constexpr int AS  = 36;
    constexpr int BS  = COUT + 8;
    constexpr int MT  = (COUT == 128) ? 4 : 2;
    uint32_t* Ah = smu;
    uint32_t* Al = smu + 128*AS;
    uint32_t* Bh = smu + 2*128*AS;
    uint32_t* Bl = Bh + 32*BS;
    float* stg = (float*)smu;
    __shared__ float sSc[128], sSh[128];

    int tid = threadIdx.x, wid = tid >> 5, lane = tid & 31;
    int gid = lane >> 2, tig = lane & 3;
    int r0 = blockIdx.x * 128;

    if constexpr (MODE == 3 || MODE == 2) {
        affine_init(pstage, gam, bet, nstat, (MODE == 3) ? CIN : 128, sSc, sSh, tid);
        __syncthreads();
    }

    int mbase = (COUT == 128) ? (wid >> 2) * 64 : (wid >> 1) * 32;
    int nbase = (COUT == 128) ? (wid & 3) * 32  : (wid & 1) * 32;

    float acc[MT][4][4];
#pragma unroll
    for (int mt = 0; mt < MT; mt++)
#pragma unroll
        for (int nt = 0; nt < 4; nt++)
#pragma unroll
            for (int u = 0; u < 4; u++) acc[mt][nt][u] = 0.f;

    for (int c = 0; c < NCH; c++) {
        if (c) __syncthreads();
        // ---- A chunk ----
        for (int e2 = tid; e2 < 128*32; e2 += 256) {
            int m = e2 >> 5, k2 = e2 & 31;
            int kc = c*64 + k2*2;
            int r = r0 + m;
            float v0, v1;
            if constexpr (MODE == 3) {
                unsigned bn = (unsigned)r / KKN;
                int b = bn >> 12;
                int j = g_idx[r];
                float2 p = *(const float2*)&Pin[(size_t)bn*CIN + kc];
                float2 q = *(const float2*)&Qin[((size_t)(b<<12) + j)*CIN + kc];
                v0 = fmaxf(fmaf(p.x + q.x, sSc[kc],   sSh[kc]),   0.f);
                v1 = fmaxf(fmaf(p.y + q.y, sSc[kc+1], sSh[kc+1]), 0.f);
            } else if constexpr (MODE == 4) {
                float2 p = *(const float2*)&Pin[(size_t)r*CIN + kc];
                v0 = p.x; v1 = p.y;
            } else {
                if (kc < 64) {
                    float2 p = *(const float2*)&Pin[(size_t)r*64 + kc];
                    v0 = p.x; v1 = p.y;
                } else {
                    int cc = kc - 64;
                    float s0 = sSc[cc], s1 = sSc[cc+1];
                    uint32_t u0 = (s0 >= 0.f) ? dmx[(size_t)r*128 + cc]   : dmn[(size_t)r*128 + cc];
                    uint32_t u1 = (s1 >= 0.f) ? dmx[(size_t)r*128 + cc+1] : dmn[(size_t)r*128 + cc+1];
                    v0 = fmaxf(fmaf(funkey(u0), s0, sSh[cc]),   0.f);
                    v1 = fmaxf(fmaf(funkey(u1), s1, sSh[cc+1]), 0.f);
                }
            }
            float r0f, r1f;
            Ah[m*AS + k2] = hpack(v0, v1, r0f, r1f);
            Al[m*AS + k2] = hpack2(r0f, r1f);
        }
        // ---- B chunk: straight copy from packed image ----
        for (int e2 = tid; e2 < 32*COUT; e2 += 256) {
            int k2 = e2 / COUT, n = e2 % COUT;
            Bh[k2*BS + n] = Wimg[(size_t)(c*32 + k2)*COUT + n];
            Bl[k2*BS + n] = Wimg[(size_t)(CIN/2)*COUT + (size_t)(c*32 + k2)*COUT + n];
        }
        __syncthreads();
        // ---- compute ----
#pragma unroll
        for (int kk = 0; kk < 4; kk++) {
            int k2b = kk*8;
            uint32_t ah[MT][4], al[MT][4], bh[4][2], bl[4][2];
#pragma unroll
            for (int mt = 0; mt < MT; mt++) {
                int rb = mbase + mt*16 + gid;
                ah[mt][0] = Ah[rb*AS + k2b + tig];
                ah[mt][1] = Ah[(rb+8)*AS + k2b + tig];
                ah[mt][2] = Ah[rb*AS + k2b + tig + 4];
                ah[mt][3] = Ah[(rb+8)*AS + k2b + tig + 4];
                al[mt][0] = Al[rb*AS + k2b + tig];
                al[mt][1] = Al[(rb+8)*AS + k2b + tig];
                al[mt][2] = Al[rb*AS + k2b + tig + 4];
                al[mt][3] = Al[(rb+8)*AS + k2b + tig + 4];
            }
#pragma unroll
            for (int nt = 0; nt < 4; nt++) {
                int cb = nbase + nt*8 + gid;
                bh[nt][0] = Bh[(k2b + tig)*BS + cb];
                bh[nt][1] = Bh[(k2b + tig + 4)*BS + cb];
                bl[nt][0] = Bl[(k2b + tig)*BS + cb];
                bl[nt][1] = Bl[(k2b + tig + 4)*BS + cb];
            }
#pragma unroll
            for (int mt = 0; mt < MT; mt++)
#pragma unroll
                for (int nt = 0; nt < 4; nt++) {
                    mma16(acc[mt][nt], ah[mt], bh[nt]);
                    mma16(acc[mt][nt], ah[mt], bl[nt]);
                    mma16(acc[mt][nt], al[mt], bh[nt]);
                }
        }
    }
    __syncthreads();
    // ---- epilogue: frags + bias -> stage ----
#pragma unroll
    for (int mt = 0; mt < MT; mt++)
#pragma unroll
        for (int nt = 0; nt < 4; nt++) {
            int row = mbase + mt*16 + gid;
            int col = nbase + nt*8 + tig*2;
            float b0 = bias[col], b1 = bias[col+1];
            stg[row*(COUT+1) + col]         = acc[mt][nt][0] + b0;
            stg[row*(COUT+1) + col + 1]     = acc[mt][nt][1] + b1;
            stg[(row+8)*(COUT+1) + col]     = acc[mt][nt][2] + b0;
            stg[(row+8)*(COUT+1) + col + 1] = acc[mt][nt][3] + b1;
        }
    __syncthreads();
    if constexpr (MODE == 3) {
        // stats + per-point max/min in one pass
        if (tid < COUT) {
            float s = 0.f, q = 0.f, mx = -3.4e38f, mn = 3.4e38f;
            int curp = r0 / KKN;
#pragma unroll 4
            for (int row = 0; row < 128; row++) {
                int p = (r0 + row) / KKN;
                if (p != curp) {
                    atomicMax(&dmx[(size_t)curp*COUT + tid], fkey(mx));
                    atomicMin(&dmn[(size_t)curp*COUT + tid], fkey(mn));
                    curp = p; mx = -3.4e38f; mn = 3.4e38f;
                }
                float v = stg[row*(COUT+1) + tid];
                s += v; q += v*v;
                mx = fmaxf(mx, v); mn = fminf(mn, v);
            }
            atomicMax(&dmx[(size_t)curp*COUT + tid], fkey(mx));
            atomicMin(&dmn[(size_t)curp*COUT + tid], fkey(mn));
            atomicAdd(&g_sum[sstage][tid], (double)s);
            atomicAdd(&g_ssq[sstage][tid], (double)q);
        }
    } else {
        if constexpr (MODE == 2) {
            if (tid < COUT) {
                float s = 0.f, q = 0.f;
#pragma unroll 8
                for (int r = 0; r < 128; r++) {
                    float v = stg[r*(COUT+1) + tid];
                    s += v; q += v*v;
                }
                atomicAdd(&g_sum[sstage][tid], (double)s);
                atomicAdd(&g_ssq[sstage][tid], (double)q);
            }
        }
        float* dst = (MODE == 4) ? Hout : g_h;
        for (int e = tid; e < 128*(COUT/4); e += 256) {
            int r = e / (COUT/4), c4 = e % (COUT/4);
            const float* p = &stg[r*(COUT+1) + c4*4];
            float4 v = make_float4(p[0], p[1], p[2], p[3]);
            *(float4*)&dst[(size_t)(r0 + r)*COUT + c4*4] = v;
        }
    }
}

// ---------------- classifier final -------------------------------------------
__global__ void cls_final_kernel(const float* __restrict__ W2,
                                 const float* __restrict__ B2,
                                 const float* __restrict__ gam,
                                 const float* __restrict__ bet,
                                 float* __restrict__ out) {
    __shared__ float sSc[128], sSh[128];
    affine_init(4, gam, bet, (float)BN_TOTAL, 128, sSc, sSh, threadIdx.x);
    __syncthreads();
    int gw   = (blockIdx.x * blockDim.x + threadIdx.x) >> 5;
    int lane = threadIdx.x & 31;
    const float* hrow = &g_h[(size_t)gw * 128];
    float p = 0.f;
#pragma unroll
    for (int q = 0; q < 4; q++) {
        int c = lane + 32*q;
        float v = fmaxf(fmaf(hrow[c], sSc[c], sSh[c]), 0.f);
        p = fmaf(v, W2[c], p);
    }
#pragma unroll
    for (int o = 16; o > 0; o >>= 1) p += __shfl_down_sync(0xffffffffu, p, o);
    if (lane == 0) out[gw] = p + B2[0];
}

// ---------------- host orchestration ----------------------------------------
extern "C" void kernel_launch(void* const* d_in, const int* in_sizes, int n_in,
                              void* d_out, int out_size) {
    const float* x      = (const float*)d_in[0];
    const float* c1_w1  = (const float*)d_in[1];
    const float* c1_b1  = (const float*)d_in[2];
    const float* c1_g1  = (const float*)d_in[3];
    const float* c1_be1 = (const float*)d_in[4];
    const float* c1_w2  = (const float*)d_in[5];
    const float* c1_b2  = (const float*)d_in[6];
    const float* c1_g2  = (const float*)d_in[7];
    const float* c1_be2 = (const float*)d_in[8];
    const float* c2_w1  = (const float*)d_in[9];
    const float* c2_b1  = (const float*)d_in[10];
    const float* c2_g1  = (const float*)d_in[11];
    const float* c2_be1 = (const float*)d_in[12];
    const float* c2_w2  = (const float*)d_in[13];
    const float* c2_b2  = (const float*)d_in[14];
    const float* c2_g2  = (const float*)d_in[15];
    const float* c2_be2 = (const float*)d_in[16];
    const float* cls_w1 = (const float*)d_in[17];
    const float* cls_b1 = (const float*)d_in[18];
    const float* cls_g1 = (const float*)d_in[19];
    const float* cls_be1= (const float*)d_in[20];
    const float* cls_w2 = (const float*)d_in[21];
    const float* cls_b2 = (const float*)d_in[22];
    float* out = (float*)d_out;

    int* idx_ptr;   cudaGetSymbolAddress((void**)&idx_ptr, g_idx);
    uint32_t* wimg; cudaGetSymbolAddress((void**)&wimg, g_wimg);
    float *p1, *q1, *p2, *q2, *zero, *x1;
    uint32_t *x1mx, *x1mn, *x2mx, *x2mn;
    cudaGetSymbolAddress((void**)&p1, g_P1);
    cudaGetSymbolAddress((void**)&q1, g_Q1);
    cudaGetSymbolAddress((void**)&p2, g_P2);
    cudaGetSymbolAddress((void**)&q2, g_Q2);
    cudaGetSymbolAddress((void**)&zero, g_zero);
    cudaGetSymbolAddress((void**)&x1, g_x1);
    cudaGetSymbolAddress((void**)&x1mx, g_x1mx);
    cudaGetSymbolAddress((void**)&x1mn, g_x1mn);
    cudaGetSymbolAddress((void**)&x2mx, g_x2mx);
    cudaGetSymbolAddress((void**)&x2mn, g_x2mn);

    const int SMB128 = (2*128*36 + 2*32*136) * 4;
    const int SMB64  = (2*128*36 + 2*32*72)  * 4;
    const int SMKNN  = (2*128*36 + 2*32*136 + 128*133 + 512) * 4;
    cudaFuncSetAttribute(tgemm_kernel<64,64,3>,   cudaFuncAttributeMaxDynamicSharedMemorySize, SMB64);
    cudaFuncSetAttribute(tgemm_kernel<64,128,4>,  cudaFuncAttributeMaxDynamicSharedMemorySize, SMB128);
    cudaFuncSetAttribute(tgemm_kernel<128,128,3>, cudaFuncAttributeMaxDynamicSharedMemorySize, SMB128);
    cudaFuncSetAttribute(tgemm_kernel<192,128,2>, cudaFuncAttributeMaxDynamicSharedMemorySize, SMB128);
    cudaFuncSetAttribute(knn64_kernel,            cudaFuncAttributeMaxDynamicSharedMemorySize, SMKNN);

    // launch order: #4 (1-based) = tgemm<64,64,3> for the ncu capture
    knn4_kernel<<<BB*(NN/128), 128>>>(x, idx_ptr);                                  // 1
    prep_kernel<<<14440, 256>>>(x, c1_w1, c1_b1, c1_w2, c2_w1, c2_w2, cls_w1, wimg);// 2
    stats1_kernel<64><<<R_EDGE/320, 256>>>(p1, q1, 0);                              // 3
    tgemm_kernel<64,64,3><<<R_EDGE/128, 256, SMB64>>>(1, 0, wimg + OFF_C1L2, c1_b2,
        c1_g1, c1_be1, (float)R_EDGE, p1, q1, nullptr, x1mx, x1mn);                 // 4 <- ncu
    finalize_x1_kernel<<<BN_TOTAL*64/256, 256>>>(c1_g2, c1_be2);                    // 5
    knn64_kernel<<<BB*32, 256, SMKNN>>>(idx_ptr);                                   // 6
    tgemm_kernel<64,128,4><<<BN_TOTAL/128, 256, SMB128>>>(-1, 0, wimg + OFF_P2, c2_b1,
        nullptr, nullptr, 0.f, x1, nullptr, p2, nullptr, nullptr);                  // 7
    tgemm_kernel<64,128,4><<<BN_TOTAL/128, 256, SMB128>>>(-1, 0, wimg + OFF_Q2, zero,
        nullptr, nullptr, 0.f, x1, nullptr, q2, nullptr, nullptr);                  // 8
    stats1_kernel<128><<<R_EDGE/320, 256>>>(p2, q2, 2);                             // 9
    tgemm_kernel<128,128,3><<<R_EDGE/128, 256, SMB128>>>(3, 2, wimg + OFF_C2L2, c2_b2,
        c2_g1, c2_be1, (float)R_EDGE, p2, q2, nullptr, x2mx, x2mn);                 // 10
    tgemm_kernel<192,128,2><<<BN_TOTAL/128, 256, SMB128>>>(4, 3, wimg + OFF_CLS, cls_b1,
        c2_g2, c2_be2, (float)R_EDGE, x1, nullptr, nullptr, x2mx, x2mn);            // 11
    cls_final_kernel<<<BN_TOTAL/8, 256>>>(cls_w2, cls_b2, cls_g1, cls_be1, out);    // 12
}